// round 1
// baseline (speedup 1.0000x reference)
#include <cuda_runtime.h>
#include <math.h>

// Problem constants
#define BB 4
#define LL 4096
#define DD 1024
#define HH 16
#define DH 64
#define MM 266

#define NROWS (BB*LL)          // 16384
#define QK_SCALE 0.1767766952966369f   // 1/1024^0.25
#define PHI_SCALE 0.06131393394849658f // 1/sqrt(266)

// ---------------- scratch (device globals; no allocation allowed) -------------
__device__ float g_qproj[NROWS*DD];
__device__ float g_kproj[NROWS*DD];
__device__ float g_vproj[NROWS*DD];
__device__ float g_qp[BB*HH*LL*MM];
__device__ float g_kp[BB*HH*LL*MM];
__device__ float g_kv[BB*HH*MM*DH];
__device__ float g_ksum[BB*HH*MM];
__device__ float g_denom[BB*HH*LL];
__device__ float g_ctx[NROWS*DD];

// ---------------- GEMM: Y = alpha * (X @ W^T + bias) -------------------------
// X: (Nr, K) row-major, W: (Nc, K) row-major, Y: (Nr, Nc)
// 128x128 tile, BK=8, 256 threads, 8x8 per thread.
__global__ __launch_bounds__(256) void gemm_bias_kernel(
    const float* __restrict__ X, const float* __restrict__ W,
    const float* __restrict__ bias, float* __restrict__ Y,
    int Nr, int K, int Nc, float alpha)
{
    __shared__ float Xs[8*128];
    __shared__ float Ws[8*128];

    int tid = threadIdx.x;
    int tx = tid & 15;          // 0..15  -> col group
    int ty = tid >> 4;          // 0..15  -> row group
    int rowBase = blockIdx.y * 128;
    int colBase = blockIdx.x * 128;

    int ldRow = tid >> 1;            // 0..127
    int ldK   = (tid & 1) * 4;       // 0 or 4

    float acc[8][8];
#pragma unroll
    for (int i = 0; i < 8; ++i)
#pragma unroll
        for (int j = 0; j < 8; ++j) acc[i][j] = 0.f;

    for (int k0 = 0; k0 < K; k0 += 8) {
        float4 xv = *(const float4*)&X[(size_t)(rowBase + ldRow) * K + k0 + ldK];
        float4 wv = *(const float4*)&W[(size_t)(colBase + ldRow) * K + k0 + ldK];
        Xs[(ldK + 0) * 128 + ldRow] = xv.x;
        Xs[(ldK + 1) * 128 + ldRow] = xv.y;
        Xs[(ldK + 2) * 128 + ldRow] = xv.z;
        Xs[(ldK + 3) * 128 + ldRow] = xv.w;
        Ws[(ldK + 0) * 128 + ldRow] = wv.x;
        Ws[(ldK + 1) * 128 + ldRow] = wv.y;
        Ws[(ldK + 2) * 128 + ldRow] = wv.z;
        Ws[(ldK + 3) * 128 + ldRow] = wv.w;
        __syncthreads();

#pragma unroll
        for (int kk = 0; kk < 8; ++kk) {
            float a[8], b[8];
#pragma unroll
            for (int i = 0; i < 8; ++i) a[i] = Xs[kk * 128 + ty * 8 + i];
#pragma unroll
            for (int j = 0; j < 8; ++j) b[j] = Ws[kk * 128 + tx * 8 + j];
#pragma unroll
            for (int i = 0; i < 8; ++i)
#pragma unroll
                for (int j = 0; j < 8; ++j) acc[i][j] += a[i] * b[j];
        }
        __syncthreads();
    }

#pragma unroll
    for (int i = 0; i < 8; ++i) {
        int row = rowBase + ty * 8 + i;
#pragma unroll
        for (int j4 = 0; j4 < 8; j4 += 4) {
            int col = colBase + tx * 8 + j4;
            float4 o;
            o.x = alpha * (acc[i][j4 + 0] + bias[col + 0]);
            o.y = alpha * (acc[i][j4 + 1] + bias[col + 1]);
            o.z = alpha * (acc[i][j4 + 2] + bias[col + 2]);
            o.w = alpha * (acc[i][j4 + 3] + bias[col + 3]);
            *(float4*)&Y[(size_t)row * Nc + col] = o;
        }
    }
}

// ---------------- phi: FAVOR+ feature map -------------------------------------
// in: proj (B, L, D) ; rf (M, DH) ; out (B, H, L, M)
// grid (B*H, L/128), block 256. RF transposed in smem [DH][268].
__global__ __launch_bounds__(256) void phi_kernel(
    const float* __restrict__ proj, const float* __restrict__ rf,
    float* __restrict__ out)
{
    extern __shared__ float sm[];
    float* rfs = sm;              // [64][268]
    float* xs  = sm + 64 * 268;   // [32][64]

    int tid = threadIdx.x;
    int bh = blockIdx.x;
    int b = bh / HH, h = bh % HH;
    int l0 = blockIdx.y * 128;

    for (int idx = tid; idx < MM * DH; idx += 256) {
        int m = idx / DH, d = idx % DH;
        rfs[d * 268 + m] = rf[idx];
    }
    __syncthreads();

    int warp = tid >> 5, lane = tid & 31;

    for (int g = 0; g < 4; ++g) {
        int lbase = l0 + g * 32;
        for (int idx = tid; idx < 32 * 64; idx += 256) {
            int r = idx >> 6, d = idx & 63;
            xs[idx] = proj[((size_t)(b * LL + lbase + r)) * DD + h * DH + d];
        }
        __syncthreads();

        for (int rr = 0; rr < 4; ++rr) {
            int r = warp * 4 + rr;
            float x[64];
#pragma unroll
            for (int d = 0; d < 64; ++d) x[d] = xs[r * 64 + d];

            float hs = 0.f;
#pragma unroll
            for (int d = 0; d < 64; ++d) hs += x[d] * x[d];
            float hval = -0.5f * hs;

            float p[9];
            float mx = -3.0e38f;
#pragma unroll
            for (int j = 0; j < 9; ++j) {
                int m = lane + 32 * j;
                float s = -3.0e38f;
                if (m < MM) {
                    s = 0.f;
#pragma unroll
                    for (int d = 0; d < 64; ++d) s += x[d] * rfs[d * 268 + m];
                }
                p[j] = s;
                mx = fmaxf(mx, s);
            }
#pragma unroll
            for (int o = 16; o > 0; o >>= 1)
                mx = fmaxf(mx, __shfl_xor_sync(0xffffffffu, mx, o));

            float base = hval - mx;
            size_t rowoff = ((size_t)bh * LL + (lbase + r)) * MM;
#pragma unroll
            for (int j = 0; j < 9; ++j) {
                int m = lane + 32 * j;
                if (m < MM)
                    out[rowoff + m] = expf(base + p[j]) * PHI_SCALE;
            }
        }
        __syncthreads();
    }
}

// ---------------- kv + ksum ----------------------------------------------------
// kv[bh][m][d] = sum_l kp[bh][l][m] * v[b][l][h*64+d] ; ksum[bh][m] = sum_l kp
// grid (9, B*H), block 256 (64 d x 4)
__global__ __launch_bounds__(256) void kv_kernel(
    const float* __restrict__ kp, const float* __restrict__ vproj,
    float* __restrict__ kv, float* __restrict__ ksum)
{
    __shared__ float kps[32 * 33];
    __shared__ float vs[32 * 64];

    int tid = threadIdx.x;
    int tx = tid & 63;
    int ty = tid >> 6;
    int bh = blockIdx.y;
    int b = bh / HH, h = bh % HH;
    int m0 = blockIdx.x * 32;

    float acc[8];
#pragma unroll
    for (int i = 0; i < 8; ++i) acc[i] = 0.f;
    float ks_acc = 0.f;

    for (int l0 = 0; l0 < LL; l0 += 32) {
        for (int idx = tid; idx < 32 * 32; idx += 256) {
            int l = idx >> 5, m = idx & 31;
            float v = 0.f;
            if (m0 + m < MM)
                v = kp[((size_t)bh * LL + l0 + l) * MM + m0 + m];
            kps[l * 33 + m] = v;
        }
        for (int idx = tid; idx < 32 * 64; idx += 256) {
            int l = idx >> 6, d = idx & 63;
            vs[idx] = vproj[((size_t)(b * LL + l0 + l)) * DD + h * DH + d];
        }
        __syncthreads();

#pragma unroll 4
        for (int l = 0; l < 32; ++l) {
            float v = vs[l * 64 + tx];
#pragma unroll
            for (int i = 0; i < 8; ++i)
                acc[i] += kps[l * 33 + ty + 4 * i] * v;
        }
        if (tid < 32) {
#pragma unroll 4
            for (int l = 0; l < 32; ++l) ks_acc += kps[l * 33 + tid];
        }
        __syncthreads();
    }

#pragma unroll
    for (int i = 0; i < 8; ++i) {
        int m = m0 + ty + 4 * i;
        if (m < MM) kv[((size_t)bh * MM + m) * DH + tx] = acc[i];
    }
    if (tid < 32 && m0 + tid < MM) ksum[bh * MM + m0 + tid] = ks_acc;
}

// ---------------- denom --------------------------------------------------------
// denom[bhl] = dot(qp_row, ksum[bh]) + 1e-6 ; 1 warp -> 8 rows
__global__ __launch_bounds__(256) void denom_kernel(
    const float* __restrict__ qp, const float* __restrict__ ksum,
    float* __restrict__ denom)
{
    int warp = (blockIdx.x * blockDim.x + threadIdx.x) >> 5;
    int lane = threadIdx.x & 31;
    int row0 = warp * 8;
    for (int r = 0; r < 8; ++r) {
        int row = row0 + r;
        int bh = row >> 12;   // / 4096
        const float* q = qp + (size_t)row * MM;
        const float* ks = ksum + bh * MM;
        float s = 0.f;
#pragma unroll
        for (int j = 0; j < 9; ++j) {
            int m = lane + 32 * j;
            if (m < MM) s += q[m] * ks[m];
        }
#pragma unroll
        for (int o = 16; o > 0; o >>= 1) s += __shfl_xor_sync(0xffffffffu, s, o);
        if (lane == 0) denom[row] = s + 1e-6f;
    }
}

// ---------------- ctx ----------------------------------------------------------
// ctx[b][l][h*64+d] = (sum_m qp[bh][l][m] * kv[bh][m][d]) / denom[bh][l]
// grid (L/64, B*H), block 256, kv tile resident in smem.
__global__ __launch_bounds__(256) void ctx_kernel(
    const float* __restrict__ qp, const float* __restrict__ kv,
    const float* __restrict__ denom, float* __restrict__ ctx)
{
    extern __shared__ float sm[];
    float* kvs = sm;              // [266][64]
    float* qps = sm + MM * DH;    // [16][268]

    int tid = threadIdx.x;
    int tx = tid & 63;
    int wy = tid >> 6;            // 0..3
    int bh = blockIdx.y;
    int b = bh / HH, h = bh % HH;
    int l0 = blockIdx.x * 64;

    for (int idx = tid; idx < MM * DH; idx += 256)
        kvs[idx] = kv[(size_t)bh * MM * DH + idx];
    __syncthreads();

    for (int g = 0; g < 4; ++g) {
        int lb = l0 + g * 16;
        for (int idx = tid; idx < 16 * MM; idx += 256) {
            int r = idx / MM, m = idx % MM;
            qps[r * 268 + m] = qp[((size_t)bh * LL + lb + r) * MM + m];
        }
        __syncthreads();

        float acc[4];
#pragma unroll
        for (int il = 0; il < 4; ++il) acc[il] = 0.f;

#pragma unroll 2
        for (int m = 0; m < MM; ++m) {
            float kvv = kvs[m * 64 + tx];
#pragma unroll
            for (int il = 0; il < 4; ++il)
                acc[il] += qps[(wy * 4 + il) * 268 + m] * kvv;
        }

#pragma unroll
        for (int il = 0; il < 4; ++il) {
            int l = lb + wy * 4 + il;
            float dnm = denom[(size_t)bh * LL + l];
            ctx[((size_t)(b * LL + l)) * DD + h * DH + tx] = acc[il] / dnm;
        }
        __syncthreads();
    }
}

// ---------------- host launcher ------------------------------------------------
extern "C" void kernel_launch(void* const* d_in, const int* in_sizes, int n_in,
                              void* d_out, int out_size)
{
    const float* query = (const float*)d_in[0];
    const float* key   = (const float*)d_in[1];
    const float* value = (const float*)d_in[2];
    const float* q_w   = (const float*)d_in[3];
    const float* q_b   = (const float*)d_in[4];
    const float* k_w   = (const float*)d_in[5];
    const float* k_b   = (const float*)d_in[6];
    const float* v_w   = (const float*)d_in[7];
    const float* v_b   = (const float*)d_in[8];
    const float* out_w = (const float*)d_in[9];
    const float* out_b = (const float*)d_in[10];
    const float* rf    = (const float*)d_in[11];
    float* out = (float*)d_out;

    float *p_qproj, *p_kproj, *p_vproj, *p_qp, *p_kp, *p_kv, *p_ksum, *p_denom, *p_ctx;
    cudaGetSymbolAddress((void**)&p_qproj, g_qproj);
    cudaGetSymbolAddress((void**)&p_kproj, g_kproj);
    cudaGetSymbolAddress((void**)&p_vproj, g_vproj);
    cudaGetSymbolAddress((void**)&p_qp, g_qp);
    cudaGetSymbolAddress((void**)&p_kp, g_kp);
    cudaGetSymbolAddress((void**)&p_kv, g_kv);
    cudaGetSymbolAddress((void**)&p_ksum, g_ksum);
    cudaGetSymbolAddress((void**)&p_denom, g_denom);
    cudaGetSymbolAddress((void**)&p_ctx, g_ctx);

    // dynamic smem sizes
    int phi_smem = (64 * 268 + 32 * 64) * sizeof(float);   // 76800
    int ctx_smem = (MM * DH + 16 * 268) * sizeof(float);   // 85248
    cudaFuncSetAttribute(phi_kernel, cudaFuncAttributeMaxDynamicSharedMemorySize, phi_smem);
    cudaFuncSetAttribute(ctx_kernel, cudaFuncAttributeMaxDynamicSharedMemorySize, ctx_smem);

    dim3 gemmGrid(DD / 128, NROWS / 128);   // (8, 128)
    gemm_bias_kernel<<<gemmGrid, 256>>>(query, q_w, q_b, p_qproj, NROWS, DD, DD, QK_SCALE);
    gemm_bias_kernel<<<gemmGrid, 256>>>(key,   k_w, k_b, p_kproj, NROWS, DD, DD, QK_SCALE);
    gemm_bias_kernel<<<gemmGrid, 256>>>(value, v_w, v_b, p_vproj, NROWS, DD, DD, 1.0f);

    dim3 phiGrid(BB * HH, LL / 128);        // (64, 32)
    phi_kernel<<<phiGrid, 256, phi_smem>>>(p_qproj, rf, p_qp);
    phi_kernel<<<phiGrid, 256, phi_smem>>>(p_kproj, rf, p_kp);

    dim3 kvGrid((MM + 31) / 32, BB * HH);   // (9, 64)
    kv_kernel<<<kvGrid, 256>>>(p_kp, p_vproj, p_kv, p_ksum);

    denom_kernel<<<(BB * HH * LL) / 64, 256>>>(p_qp, p_ksum, p_denom);

    dim3 ctxGrid(LL / 64, BB * HH);         // (64, 64)
    ctx_kernel<<<ctxGrid, 256, ctx_smem>>>(p_qp, p_kv, p_denom, p_ctx);

    gemm_bias_kernel<<<gemmGrid, 256>>>(p_ctx, out_w, out_b, out, NROWS, DD, DD, 1.0f);
}

// round 3
// speedup vs baseline: 1.4575x; 1.4575x over previous
#include <cuda_runtime.h>
#include <math.h>
#include <stdint.h>

// Problem constants
#define BB 4
#define LL 4096
#define DD 1024
#define HH 16
#define DH 64
#define MM 266

#define NROWS (BB*LL)          // 16384
#define QK_SCALE 0.1767766952966369f   // 1/1024^0.25
#define PHI_SCALE 0.06131393394849658f // 1/sqrt(266)

// ---------------- scratch (device globals; no allocation allowed) -------------
__device__ float g_qproj[NROWS*DD];
__device__ float g_kproj[NROWS*DD];
__device__ float g_vproj[NROWS*DD];
__device__ float g_qp[BB*HH*LL*MM];
__device__ float g_kp[BB*HH*LL*MM];
__device__ float g_kv[BB*HH*MM*DH];
__device__ float g_ksum[BB*HH*MM];
__device__ float g_denom[BB*HH*LL];
__device__ float g_ctx[NROWS*DD];

// ---------------- TF32 tensor-core GEMM: Y = alpha * (X @ W^T + bias) ---------
// X: (16384, 1024) row-major, W: (1024, 1024) row-major, Y: (16384, 1024)
// 128x128x16 tile, 256 threads, warp grid 2x4, warp tile 64x32 (4x4 m16n8k8).
#define SMPAD 20   // 128-row tiles padded to 20 floats/row: conflict-free frags

__device__ __forceinline__ uint32_t cvt_tf32(float x) {
    uint32_t r;
    asm("cvt.rna.tf32.f32 %0, %1;" : "=r"(r) : "f"(x));
    return r;
}

__device__ __forceinline__ void cp16(uint32_t s, const void* g) {
    asm volatile("cp.async.cg.shared.global [%0], [%1], 16;" :: "r"(s), "l"(g));
}
__device__ __forceinline__ void cp_commit() {
    asm volatile("cp.async.commit_group;");
}
template<int N> __device__ __forceinline__ void cp_wait() {
    asm volatile("cp.async.wait_group %0;" :: "n"(N));
}

__device__ __forceinline__ void mma_tf32(float* c, const uint32_t* a, const uint32_t* b) {
    asm volatile(
        "mma.sync.aligned.m16n8k8.row.col.f32.tf32.tf32.f32 "
        "{%0,%1,%2,%3},{%4,%5,%6,%7},{%8,%9},{%0,%1,%2,%3};"
        : "+f"(c[0]), "+f"(c[1]), "+f"(c[2]), "+f"(c[3])
        : "r"(a[0]), "r"(a[1]), "r"(a[2]), "r"(a[3]), "r"(b[0]), "r"(b[1]));
}

__global__ __launch_bounds__(256) void gemm_tf32_kernel(
    const float* __restrict__ X, const float* __restrict__ W,
    const float* __restrict__ bias, float* __restrict__ Y, float alpha)
{
    __shared__ __align__(16) float As[2][128 * SMPAD];
    __shared__ __align__(16) float Bs[2][128 * SMPAD];

    int tid = threadIdx.x;
    int lane = tid & 31, warp = tid >> 5;
    int wm = warp >> 2, wn = warp & 3;         // 2 x 4 warp grid
    int rowBase = blockIdx.y * 128, colBase = blockIdx.x * 128;

    // each thread copies 2 float4 for A and 2 for B per stage
    int f0 = tid * 2;
    int lr0 = f0 >> 2,      lc0 = (f0 & 3) * 4;
    int lr1 = (f0 + 1) >> 2, lc1 = ((f0 + 1) & 3) * 4;

    const float* gA0 = X + (size_t)(rowBase + lr0) * DD + lc0;
    const float* gA1 = X + (size_t)(rowBase + lr1) * DD + lc1;
    const float* gB0 = W + (size_t)(colBase + lr0) * DD + lc0;
    const float* gB1 = W + (size_t)(colBase + lr1) * DD + lc1;

    uint32_t sA0[2], sA1[2], sB0[2], sB1[2];
#pragma unroll
    for (int b = 0; b < 2; ++b) {
        sA0[b] = (uint32_t)__cvta_generic_to_shared(&As[b][lr0 * SMPAD + lc0]);
        sA1[b] = (uint32_t)__cvta_generic_to_shared(&As[b][lr1 * SMPAD + lc1]);
        sB0[b] = (uint32_t)__cvta_generic_to_shared(&Bs[b][lr0 * SMPAD + lc0]);
        sB1[b] = (uint32_t)__cvta_generic_to_shared(&Bs[b][lr1 * SMPAD + lc1]);
    }

    float acc[4][4][4];
#pragma unroll
    for (int mt = 0; mt < 4; ++mt)
#pragma unroll
        for (int nt = 0; nt < 4; ++nt)
#pragma unroll
            for (int i = 0; i < 4; ++i) acc[mt][nt][i] = 0.f;

    // prologue: stage 0
    cp16(sA0[0], gA0); cp16(sA1[0], gA1);
    cp16(sB0[0], gB0); cp16(sB1[0], gB1);
    cp_commit();

    const int NK = DD / 16;   // 64
    for (int kt = 0; kt < NK; ++kt) {
        int buf = kt & 1;
        if (kt + 1 < NK) {
            int off = (kt + 1) * 16;
            cp16(sA0[buf ^ 1], gA0 + off); cp16(sA1[buf ^ 1], gA1 + off);
            cp16(sB0[buf ^ 1], gB0 + off); cp16(sB1[buf ^ 1], gB1 + off);
            cp_commit();
            cp_wait<1>();
        } else {
            cp_wait<0>();
        }
        __syncthreads();

#pragma unroll
        for (int ks = 0; ks < 2; ++ks) {
            int kk = ks * 8 + (lane & 3);
            int r = lane >> 2;
            uint32_t a[4][4], b[4][2];
#pragma unroll
            for (int mt = 0; mt < 4; ++mt) {
                int ar = wm * 64 + mt * 16 + r;
                a[mt][0] = cvt_tf32(As[buf][ar * SMPAD + kk]);
                a[mt][1] = cvt_tf32(As[buf][(ar + 8) * SMPAD + kk]);
                a[mt][2] = cvt_tf32(As[buf][ar * SMPAD + kk + 4]);
                a[mt][3] = cvt_tf32(As[buf][(ar + 8) * SMPAD + kk + 4]);
            }
#pragma unroll
            for (int nt = 0; nt < 4; ++nt) {
                int br = wn * 32 + nt * 8 + r;
                b[nt][0] = cvt_tf32(Bs[buf][br * SMPAD + kk]);
                b[nt][1] = cvt_tf32(Bs[buf][br * SMPAD + kk + 4]);
            }
#pragma unroll
            for (int mt = 0; mt < 4; ++mt)
#pragma unroll
                for (int nt = 0; nt < 4; ++nt)
                    mma_tf32(acc[mt][nt], a[mt], b[nt]);
        }
        __syncthreads();
    }

    // epilogue
#pragma unroll
    for (int mt = 0; mt < 4; ++mt) {
        int r0 = rowBase + wm * 64 + mt * 16 + (lane >> 2);
#pragma unroll
        for (int nt = 0; nt < 4; ++nt) {
            int c = colBase + wn * 32 + nt * 8 + 2 * (lane & 3);
            float2 bv = *(const float2*)&bias[c];
            float2 o0, o1;
            o0.x = alpha * (acc[mt][nt][0] + bv.x);
            o0.y = alpha * (acc[mt][nt][1] + bv.y);
            o1.x = alpha * (acc[mt][nt][2] + bv.x);
            o1.y = alpha * (acc[mt][nt][3] + bv.y);
            *(float2*)&Y[(size_t)r0 * DD + c] = o0;
            *(float2*)&Y[(size_t)(r0 + 8) * DD + c] = o1;
        }
    }
}

// ---------------- phi: FAVOR+ feature map -------------------------------------
__global__ __launch_bounds__(256) void phi_kernel(
    const float* __restrict__ proj, const float* __restrict__ rf,
    float* __restrict__ out)
{
    extern __shared__ float sm[];
    float* rfs = sm;              // [64][268]
    float* xs  = sm + 64 * 268;   // [32][64]

    int tid = threadIdx.x;
    int bh = blockIdx.x;
    int b = bh / HH, h = bh % HH;
    int l0 = blockIdx.y * 128;

    for (int idx = tid; idx < MM * DH; idx += 256) {
        int m = idx / DH, d = idx % DH;
        rfs[d * 268 + m] = rf[idx];
    }
    __syncthreads();

    int warp = tid >> 5, lane = tid & 31;

    for (int g = 0; g < 4; ++g) {
        int lbase = l0 + g * 32;
        for (int idx = tid; idx < 32 * 64; idx += 256) {
            int r = idx >> 6, d = idx & 63;
            xs[idx] = proj[((size_t)(b * LL + lbase + r)) * DD + h * DH + d];
        }
        __syncthreads();

        for (int rr = 0; rr < 4; ++rr) {
            int r = warp * 4 + rr;
            float x[64];
#pragma unroll
            for (int d = 0; d < 64; ++d) x[d] = xs[r * 64 + d];

            float hs = 0.f;
#pragma unroll
            for (int d = 0; d < 64; ++d) hs += x[d] * x[d];
            float hval = -0.5f * hs;

            float p[9];
            float mx = -3.0e38f;
#pragma unroll
            for (int j = 0; j < 9; ++j) {
                int m = lane + 32 * j;
                float s = -3.0e38f;
                if (m < MM) {
                    s = 0.f;
#pragma unroll
                    for (int d = 0; d < 64; ++d) s += x[d] * rfs[d * 268 + m];
                }
                p[j] = s;
                mx = fmaxf(mx, s);
            }
#pragma unroll
            for (int o = 16; o > 0; o >>= 1)
                mx = fmaxf(mx, __shfl_xor_sync(0xffffffffu, mx, o));

            float base = hval - mx;
            size_t rowoff = ((size_t)bh * LL + (lbase + r)) * MM;
#pragma unroll
            for (int j = 0; j < 9; ++j) {
                int m = lane + 32 * j;
                if (m < MM)
                    out[rowoff + m] = expf(base + p[j]) * PHI_SCALE;
            }
        }
        __syncthreads();
    }
}

// ---------------- kv + ksum ----------------------------------------------------
__global__ __launch_bounds__(256) void kv_kernel(
    const float* __restrict__ kp, const float* __restrict__ vproj,
    float* __restrict__ kv, float* __restrict__ ksum)
{
    __shared__ float kps[32 * 33];
    __shared__ float vs[32 * 64];

    int tid = threadIdx.x;
    int tx = tid & 63;
    int ty = tid >> 6;
    int bh = blockIdx.y;
    int b = bh / HH, h = bh % HH;
    int m0 = blockIdx.x * 32;

    float acc[8];
#pragma unroll
    for (int i = 0; i < 8; ++i) acc[i] = 0.f;
    float ks_acc = 0.f;

    for (int l0 = 0; l0 < LL; l0 += 32) {
        for (int idx = tid; idx < 32 * 32; idx += 256) {
            int l = idx >> 5, m = idx & 31;
            float v = 0.f;
            if (m0 + m < MM)
                v = kp[((size_t)bh * LL + l0 + l) * MM + m0 + m];
            kps[l * 33 + m] = v;
        }
        for (int idx = tid; idx < 32 * 64; idx += 256) {
            int l = idx >> 6, d = idx & 63;
            vs[idx] = vproj[((size_t)(b * LL + l0 + l)) * DD + h * DH + d];
        }
        __syncthreads();

#pragma unroll 4
        for (int l = 0; l < 32; ++l) {
            float v = vs[l * 64 + tx];
#pragma unroll
            for (int i = 0; i < 8; ++i)
                acc[i] += kps[l * 33 + ty + 4 * i] * v;
        }
        if (tid < 32) {
#pragma unroll 4
            for (int l = 0; l < 32; ++l) ks_acc += kps[l * 33 + tid];
        }
        __syncthreads();
    }

#pragma unroll
    for (int i = 0; i < 8; ++i) {
        int m = m0 + ty + 4 * i;
        if (m < MM) kv[((size_t)bh * MM + m) * DH + tx] = acc[i];
    }
    if (tid < 32 && m0 + tid < MM) ksum[bh * MM + m0 + tid] = ks_acc;
}

// ---------------- denom --------------------------------------------------------
__global__ __launch_bounds__(256) void denom_kernel(
    const float* __restrict__ qp, const float* __restrict__ ksum,
    float* __restrict__ denom)
{
    int warp = (blockIdx.x * blockDim.x + threadIdx.x) >> 5;
    int lane = threadIdx.x & 31;
    int row0 = warp * 8;
    for (int r = 0; r < 8; ++r) {
        int row = row0 + r;
        int bh = row >> 12;
        const float* q = qp + (size_t)row * MM;
        const float* ks = ksum + bh * MM;
        float s = 0.f;
#pragma unroll
        for (int j = 0; j < 9; ++j) {
            int m = lane + 32 * j;
            if (m < MM) s += q[m] * ks[m];
        }
#pragma unroll
        for (int o = 16; o > 0; o >>= 1) s += __shfl_xor_sync(0xffffffffu, s, o);
        if (lane == 0) denom[row] = s + 1e-6f;
    }
}

// ---------------- ctx ----------------------------------------------------------
__global__ __launch_bounds__(256) void ctx_kernel(
    const float* __restrict__ qp, const float* __restrict__ kv,
    const float* __restrict__ denom, float* __restrict__ ctx)
{
    extern __shared__ float sm[];
    float* kvs = sm;              // [266][64]
    float* qps = sm + MM * DH;    // [16][268]

    int tid = threadIdx.x;
    int tx = tid & 63;
    int wy = tid >> 6;
    int bh = blockIdx.y;
    int b = bh / HH, h = bh % HH;
    int l0 = blockIdx.x * 64;

    for (int idx = tid; idx < MM * DH; idx += 256)
        kvs[idx] = kv[(size_t)bh * MM * DH + idx];
    __syncthreads();

    for (int g = 0; g < 4; ++g) {
        int lb = l0 + g * 16;
        for (int idx = tid; idx < 16 * MM; idx += 256) {
            int r = idx / MM, m = idx % MM;
            qps[r * 268 + m] = qp[((size_t)bh * LL + lb + r) * MM + m];
        }
        __syncthreads();

        float acc[4];
#pragma unroll
        for (int il = 0; il < 4; ++il) acc[il] = 0.f;

#pragma unroll 2
        for (int m = 0; m < MM; ++m) {
            float kvv = kvs[m * 64 + tx];
#pragma unroll
            for (int il = 0; il < 4; ++il)
                acc[il] += qps[(wy * 4 + il) * 268 + m] * kvv;
        }

#pragma unroll
        for (int il = 0; il < 4; ++il) {
            int l = lb + wy * 4 + il;
            float dnm = denom[(size_t)bh * LL + l];
            ctx[((size_t)(b * LL + l)) * DD + h * DH + tx] = acc[il] / dnm;
        }
        __syncthreads();
    }
}

// ---------------- host launcher ------------------------------------------------
extern "C" void kernel_launch(void* const* d_in, const int* in_sizes, int n_in,
                              void* d_out, int out_size)
{
    const float* query = (const float*)d_in[0];
    const float* key   = (const float*)d_in[1];
    const float* value = (const float*)d_in[2];
    const float* q_w   = (const float*)d_in[3];
    const float* q_b   = (const float*)d_in[4];
    const float* k_w   = (const float*)d_in[5];
    const float* k_b   = (const float*)d_in[6];
    const float* v_w   = (const float*)d_in[7];
    const float* v_b   = (const float*)d_in[8];
    const float* out_w = (const float*)d_in[9];
    const float* out_b = (const float*)d_in[10];
    const float* rf    = (const float*)d_in[11];
    float* out = (float*)d_out;

    float *p_qproj, *p_kproj, *p_vproj, *p_qp, *p_kp, *p_kv, *p_ksum, *p_denom, *p_ctx;
    cudaGetSymbolAddress((void**)&p_qproj, g_qproj);
    cudaGetSymbolAddress((void**)&p_kproj, g_kproj);
    cudaGetSymbolAddress((void**)&p_vproj, g_vproj);
    cudaGetSymbolAddress((void**)&p_qp, g_qp);
    cudaGetSymbolAddress((void**)&p_kp, g_kp);
    cudaGetSymbolAddress((void**)&p_kv, g_kv);
    cudaGetSymbolAddress((void**)&p_ksum, g_ksum);
    cudaGetSymbolAddress((void**)&p_denom, g_denom);
    cudaGetSymbolAddress((void**)&p_ctx, g_ctx);

    int phi_smem = (64 * 268 + 32 * 64) * sizeof(float);
    int ctx_smem = (MM * DH + 16 * 268) * sizeof(float);
    cudaFuncSetAttribute(phi_kernel, cudaFuncAttributeMaxDynamicSharedMemorySize, phi_smem);
    cudaFuncSetAttribute(ctx_kernel, cudaFuncAttributeMaxDynamicSharedMemorySize, ctx_smem);

    dim3 gemmGrid(DD / 128, NROWS / 128);   // (8, 128)
    gemm_tf32_kernel<<<gemmGrid, 256>>>(query, q_w, q_b, p_qproj, QK_SCALE);
    gemm_tf32_kernel<<<gemmGrid, 256>>>(key,   k_w, k_b, p_kproj, QK_SCALE);
    gemm_tf32_kernel<<<gemmGrid, 256>>>(value, v_w, v_b, p_vproj, 1.0f);

    dim3 phiGrid(BB * HH, LL / 128);        // (64, 32)
    phi_kernel<<<phiGrid, 256, phi_smem>>>(p_qproj, rf, p_qp);
    phi_kernel<<<phiGrid, 256, phi_smem>>>(p_kproj, rf, p_kp);

    dim3 kvGrid((MM + 31) / 32, BB * HH);   // (9, 64)
    kv_kernel<<<kvGrid, 256>>>(p_kp, p_vproj, p_kv, p_ksum);

    denom_kernel<<<(BB * HH * LL) / 64, 256>>>(p_qp, p_ksum, p_denom);

    dim3 ctxGrid(LL / 64, BB * HH);         // (64, 64)
    ctx_kernel<<<ctxGrid, 256, ctx_smem>>>(p_qp, p_kv, p_denom, p_ctx);

    gemm_tf32_kernel<<<gemmGrid, 256>>>(p_ctx, out_w, out_b, out, 1.0f);
}

// round 4
// speedup vs baseline: 4.2460x; 2.9132x over previous
#include <cuda_runtime.h>
#include <math.h>
#include <stdint.h>

// Problem constants
#define BB 4
#define LL 4096
#define DD 1024
#define HH 16
#define DH 64
#define MM 266
#define MP 272                 // M padded to 272 (34 n8-tiles)

#define NROWS (BB*LL)          // 16384
#define GROWS (BB*LL*HH)       // 262144 (b,l,h) rows
#define QK_SCALE 0.1767766952966369f   // 1/1024^0.25
#define PHI_SCALE 0.06131393394849658f // 1/sqrt(266)

// ---------------- scratch (device globals; no allocation allowed) -------------
__device__ float g_qproj[NROWS*DD];
__device__ float g_kproj[NROWS*DD];
__device__ float g_vproj[NROWS*DD];
__device__ float g_qp[(size_t)BB*HH*LL*MP];     // (bh, l, 272) fp32
__device__ float g_kp[(size_t)BB*HH*LL*MP];
__device__ float g_kvpart[4*BB*HH*80*276];      // k-split partials of kvT
__device__ float g_kvT[BB*HH*80*276];           // kvT[bh][d(80)][m(276)], row64=ksum
__device__ float g_ctx[NROWS*DD];

// ---------------- common MMA helpers ------------------------------------------
__device__ __forceinline__ uint32_t cvt_tf32(float x) {
    uint32_t r;
    asm("cvt.rna.tf32.f32 %0, %1;" : "=r"(r) : "f"(x));
    return r;
}
__device__ __forceinline__ void cp16(uint32_t s, const void* g) {
    asm volatile("cp.async.cg.shared.global [%0], [%1], 16;" :: "r"(s), "l"(g));
}
__device__ __forceinline__ void cp_commit() {
    asm volatile("cp.async.commit_group;");
}
template<int N> __device__ __forceinline__ void cp_wait() {
    asm volatile("cp.async.wait_group %0;" :: "n"(N));
}
__device__ __forceinline__ void mma_tf32(float* c, const uint32_t* a, const uint32_t* b) {
    asm volatile(
        "mma.sync.aligned.m16n8k8.row.col.f32.tf32.tf32.f32 "
        "{%0,%1,%2,%3},{%4,%5,%6,%7},{%8,%9},{%0,%1,%2,%3};"
        : "+f"(c[0]), "+f"(c[1]), "+f"(c[2]), "+f"(c[3])
        : "r"(a[0]), "r"(a[1]), "r"(a[2]), "r"(a[3]), "r"(b[0]), "r"(b[1]));
}

// ---------------- TF32 tensor-core GEMM: Y = alpha * (X @ W^T + bias) ---------
#define SMPAD 20

__global__ __launch_bounds__(256) void gemm_tf32_kernel(
    const float* __restrict__ X, const float* __restrict__ W,
    const float* __restrict__ bias, float* __restrict__ Y, float alpha)
{
    __shared__ __align__(16) float As[2][128 * SMPAD];
    __shared__ __align__(16) float Bs[2][128 * SMPAD];

    int tid = threadIdx.x;
    int lane = tid & 31, warp = tid >> 5;
    int wm = warp >> 2, wn = warp & 3;
    int rowBase = blockIdx.y * 128, colBase = blockIdx.x * 128;

    int f0 = tid * 2;
    int lr0 = f0 >> 2,      lc0 = (f0 & 3) * 4;
    int lr1 = (f0 + 1) >> 2, lc1 = ((f0 + 1) & 3) * 4;

    const float* gA0 = X + (size_t)(rowBase + lr0) * DD + lc0;
    const float* gA1 = X + (size_t)(rowBase + lr1) * DD + lc1;
    const float* gB0 = W + (size_t)(colBase + lr0) * DD + lc0;
    const float* gB1 = W + (size_t)(colBase + lr1) * DD + lc1;

    uint32_t sA0[2], sA1[2], sB0[2], sB1[2];
#pragma unroll
    for (int b = 0; b < 2; ++b) {
        sA0[b] = (uint32_t)__cvta_generic_to_shared(&As[b][lr0 * SMPAD + lc0]);
        sA1[b] = (uint32_t)__cvta_generic_to_shared(&As[b][lr1 * SMPAD + lc1]);
        sB0[b] = (uint32_t)__cvta_generic_to_shared(&Bs[b][lr0 * SMPAD + lc0]);
        sB1[b] = (uint32_t)__cvta_generic_to_shared(&Bs[b][lr1 * SMPAD + lc1]);
    }

    float acc[4][4][4];
#pragma unroll
    for (int mt = 0; mt < 4; ++mt)
#pragma unroll
        for (int nt = 0; nt < 4; ++nt)
#pragma unroll
            for (int i = 0; i < 4; ++i) acc[mt][nt][i] = 0.f;

    cp16(sA0[0], gA0); cp16(sA1[0], gA1);
    cp16(sB0[0], gB0); cp16(sB1[0], gB1);
    cp_commit();

    const int NK = DD / 16;
    for (int kt = 0; kt < NK; ++kt) {
        int buf = kt & 1;
        if (kt + 1 < NK) {
            int off = (kt + 1) * 16;
            cp16(sA0[buf ^ 1], gA0 + off); cp16(sA1[buf ^ 1], gA1 + off);
            cp16(sB0[buf ^ 1], gB0 + off); cp16(sB1[buf ^ 1], gB1 + off);
            cp_commit();
            cp_wait<1>();
        } else {
            cp_wait<0>();
        }
        __syncthreads();

#pragma unroll
        for (int ks = 0; ks < 2; ++ks) {
            int kk = ks * 8 + (lane & 3);
            int r = lane >> 2;
            uint32_t a[4][4], b[4][2];
#pragma unroll
            for (int mt = 0; mt < 4; ++mt) {
                int ar = wm * 64 + mt * 16 + r;
                a[mt][0] = cvt_tf32(As[buf][ar * SMPAD + kk]);
                a[mt][1] = cvt_tf32(As[buf][(ar + 8) * SMPAD + kk]);
                a[mt][2] = cvt_tf32(As[buf][ar * SMPAD + kk + 4]);
                a[mt][3] = cvt_tf32(As[buf][(ar + 8) * SMPAD + kk + 4]);
            }
#pragma unroll
            for (int nt = 0; nt < 4; ++nt) {
                int br = wn * 32 + nt * 8 + r;
                b[nt][0] = cvt_tf32(Bs[buf][br * SMPAD + kk]);
                b[nt][1] = cvt_tf32(Bs[buf][br * SMPAD + kk + 4]);
            }
#pragma unroll
            for (int mt = 0; mt < 4; ++mt)
#pragma unroll
                for (int nt = 0; nt < 4; ++nt)
                    mma_tf32(acc[mt][nt], a[mt], b[nt]);
        }
        __syncthreads();
    }

#pragma unroll
    for (int mt = 0; mt < 4; ++mt) {
        int r0 = rowBase + wm * 64 + mt * 16 + (lane >> 2);
#pragma unroll
        for (int nt = 0; nt < 4; ++nt) {
            int c = colBase + wn * 32 + nt * 8 + 2 * (lane & 3);
            float2 bv = *(const float2*)&bias[c];
            float2 o0, o1;
            o0.x = alpha * (acc[mt][nt][0] + bv.x);
            o0.y = alpha * (acc[mt][nt][1] + bv.y);
            o1.x = alpha * (acc[mt][nt][2] + bv.x);
            o1.y = alpha * (acc[mt][nt][3] + bv.y);
            *(float2*)&Y[(size_t)r0 * DD + c] = o0;
            *(float2*)&Y[(size_t)(r0 + 8) * DD + c] = o1;
        }
    }
}

// ---------------- phi as TF32 MMA GEMM + fused max/exp -------------------------
// rows g = (b*LL+l)*16 + h ; A = proj rows (64), B = rf (col-major), N=272
// out: qp[((b*16+h)*LL + l)*272 + m] fp32 ; pad cols 266..271 = 0
__global__ __launch_bounds__(256) void phi_gemm_kernel(
    const float* __restrict__ proj, const float* __restrict__ rf,
    float* __restrict__ out)
{
    extern __shared__ float sm[];
    float* rfs = sm;                 // [272][68] tf32-rounded
    float* As  = sm + 272 * 68;      // [128][68] raw fp32
    float* hs  = As + 128 * 68;      // [128]

    int tid = threadIdx.x;
    int lane = tid & 31, w = tid >> 5;
    int g0 = blockIdx.x * 128;

    // load rf -> rfs (tf32-rounded), pad rows 266..271 with 0
    for (int idx = tid; idx < 266 * 16; idx += 256) {
        int m = idx >> 4, q = (idx & 15) * 4;
        float4 v = *(const float4*)&rf[m * 64 + q];
        rfs[m * 68 + q + 0] = __uint_as_float(cvt_tf32(v.x));
        rfs[m * 68 + q + 1] = __uint_as_float(cvt_tf32(v.y));
        rfs[m * 68 + q + 2] = __uint_as_float(cvt_tf32(v.z));
        rfs[m * 68 + q + 3] = __uint_as_float(cvt_tf32(v.w));
    }
    for (int idx = tid; idx < 6 * 64; idx += 256) {
        int m = 266 + idx / 64, d = idx % 64;
        rfs[m * 68 + d] = 0.f;
    }
    // load A rows (raw fp32)
    for (int idx = tid; idx < 128 * 16; idx += 256) {
        int r = idx >> 4, q = (idx & 15) * 4;
        float4 v = *(const float4*)&proj[(size_t)(g0 + r) * 64 + q];
        *(float4*)&As[r * 68 + q] = v;
    }
    __syncthreads();
    // row h values
    if (tid < 128) {
        float s = 0.f;
#pragma unroll
        for (int d = 0; d < 64; ++d) { float x = As[tid * 68 + d]; s += x * x; }
        hs[tid] = -0.5f * s;
    }
    __syncthreads();

    float acc[34][4];
#pragma unroll
    for (int t = 0; t < 34; ++t)
#pragma unroll
        for (int i = 0; i < 4; ++i) acc[t][i] = 0.f;

    int r = lane >> 2;
    int arow = w * 16 + r;
#pragma unroll
    for (int ks = 0; ks < 8; ++ks) {
        int kk = ks * 8 + (lane & 3);
        uint32_t a[4];
        a[0] = cvt_tf32(As[arow * 68 + kk]);
        a[1] = cvt_tf32(As[(arow + 8) * 68 + kk]);
        a[2] = cvt_tf32(As[arow * 68 + kk + 4]);
        a[3] = cvt_tf32(As[(arow + 8) * 68 + kk + 4]);
#pragma unroll
        for (int t = 0; t < 34; ++t) {
            uint32_t b[2];
            int br = t * 8 + r;
            b[0] = __float_as_uint(rfs[br * 68 + kk]);
            b[1] = __float_as_uint(rfs[br * 68 + kk + 4]);
            mma_tf32(acc[t], a, b);
        }
    }

    // row max over real 266 cols
    float mx0 = -3.0e38f, mx1 = -3.0e38f;
#pragma unroll
    for (int t = 0; t < 34; ++t) {
        int c0 = t * 8 + 2 * (lane & 3);
        if (c0 < 266)     { mx0 = fmaxf(mx0, acc[t][0]); mx1 = fmaxf(mx1, acc[t][2]); }
        if (c0 + 1 < 266) { mx0 = fmaxf(mx0, acc[t][1]); mx1 = fmaxf(mx1, acc[t][3]); }
    }
    mx0 = fmaxf(mx0, __shfl_xor_sync(0xffffffffu, mx0, 1));
    mx0 = fmaxf(mx0, __shfl_xor_sync(0xffffffffu, mx0, 2));
    mx1 = fmaxf(mx1, __shfl_xor_sync(0xffffffffu, mx1, 1));
    mx1 = fmaxf(mx1, __shfl_xor_sync(0xffffffffu, mx1, 2));

    float h0 = hs[arow], h1 = hs[arow + 8];

    int gr0 = g0 + arow, gr1 = g0 + arow + 8;
    int b0i = gr0 >> 16, rem0 = gr0 & 65535, l0 = rem0 >> 4, hh0 = rem0 & 15;
    int b1i = gr1 >> 16, rem1 = gr1 & 65535, l1 = rem1 >> 4, hh1 = rem1 & 15;
    float* d0p = out + ((size_t)(b0i * 16 + hh0) * LL + l0) * MP;
    float* d1p = out + ((size_t)(b1i * 16 + hh1) * LL + l1) * MP;

#pragma unroll
    for (int t = 0; t < 34; ++t) {
        int c0 = t * 8 + 2 * (lane & 3);
        float2 v0, v1;
        v0.x = (c0     < 266) ? expf(h0 + acc[t][0] - mx0) * PHI_SCALE : 0.f;
        v0.y = (c0 + 1 < 266) ? expf(h0 + acc[t][1] - mx0) * PHI_SCALE : 0.f;
        v1.x = (c0     < 266) ? expf(h1 + acc[t][2] - mx1) * PHI_SCALE : 0.f;
        v1.y = (c0 + 1 < 266) ? expf(h1 + acc[t][3] - mx1) * PHI_SCALE : 0.f;
        *(float2*)&d0p[c0] = v0;
        *(float2*)&d1p[c0] = v1;
    }
}

// ---------------- kv as TF32 MMA: kvT[d][m] = sum_l vT[d][l]*kp[l][m] ----------
// A = vT (transposed in smem, row 64 = ones -> ksum), B = kp (stored [k][n]).
// grid (4 ksplit, 64 bh); partial outputs, reduced by kv_reduce_kernel.
__global__ __launch_bounds__(256) void kv_gemm_kernel(
    const float* __restrict__ kp, const float* __restrict__ vproj,
    float* __restrict__ kvpart)
{
    __shared__ float kps[32 * 272];   // [l][m] raw
    __shared__ float vsT[80 * 36];    // [d][l] raw, row64=1, 65..79=0

    int tid = threadIdx.x;
    int lane = tid & 31, w = tid >> 5;
    int split = blockIdx.x, bh = blockIdx.y;
    int b = bh >> 4, h = bh & 15;

    // init constant rows of vsT
    for (int idx = tid; idx < 16 * 36; idx += 256)
        vsT[64 * 36 + idx] = (idx < 32) ? 1.0f : 0.f;   // row 64 = ones (cols 0..31), rows 65..79 = 0
    // note: row 64 cols 32..35 unused by frags (k<32)

    int ntiles = (w < 2) ? 5 : 4;
    float acc[5][5][4];
#pragma unroll
    for (int mt = 0; mt < 5; ++mt)
#pragma unroll
        for (int j = 0; j < 5; ++j)
#pragma unroll
            for (int i = 0; i < 4; ++i) acc[mt][j][i] = 0.f;

    int lbase = split * 1024;
    for (int ch = 0; ch < 32; ++ch) {
        int l0 = lbase + ch * 32;
        __syncthreads();
        // load kp chunk [32][272]
        for (int idx = tid; idx < 32 * 68; idx += 256) {
            int m4 = idx % 68, l = idx / 68;
            float4 v = *(const float4*)&kp[((size_t)bh * LL + l0 + l) * MP + 4 * m4];
            *(float4*)&kps[l * 272 + 4 * m4] = v;
        }
        // transpose v chunk into vsT rows 0..63
        for (int idx = tid; idx < 512; idx += 256) {
            int d4 = idx & 15, l = idx >> 4;
            float4 v = *(const float4*)&vproj[((size_t)(b * LL + l0 + l)) * DD + h * DH + 4 * d4];
            vsT[(4 * d4 + 0) * 36 + l] = v.x;
            vsT[(4 * d4 + 1) * 36 + l] = v.y;
            vsT[(4 * d4 + 2) * 36 + l] = v.z;
            vsT[(4 * d4 + 3) * 36 + l] = v.w;
        }
        __syncthreads();

#pragma unroll
        for (int ks = 0; ks < 4; ++ks) {
            int kk = ks * 8 + (lane & 3);
            int r = lane >> 2;
            uint32_t a[5][4];
#pragma unroll
            for (int mt = 0; mt < 5; ++mt) {
                int ar = mt * 16 + r;
                a[mt][0] = cvt_tf32(vsT[ar * 36 + kk]);
                a[mt][1] = cvt_tf32(vsT[(ar + 8) * 36 + kk]);
                a[mt][2] = cvt_tf32(vsT[ar * 36 + kk + 4]);
                a[mt][3] = cvt_tf32(vsT[(ar + 8) * 36 + kk + 4]);
            }
#pragma unroll
            for (int j = 0; j < 5; ++j) {
                if (j >= ntiles) break;
                int t = (j < 4) ? (w + 8 * j) : (32 + w);
                uint32_t bfr[2];
                bfr[0] = cvt_tf32(kps[kk * 272 + t * 8 + r]);
                bfr[1] = cvt_tf32(kps[(kk + 4) * 272 + t * 8 + r]);
#pragma unroll
                for (int mt = 0; mt < 5; ++mt)
                    mma_tf32(acc[mt][j], a[mt], bfr);
            }
        }
    }

    // write partials
    float* dst = kvpart + (size_t)(split * 64 + bh) * 80 * 276;
#pragma unroll
    for (int mt = 0; mt < 5; ++mt) {
        int d0 = mt * 16 + (lane >> 2);
#pragma unroll
        for (int j = 0; j < 5; ++j) {
            if (j >= ntiles) break;
            int t = (j < 4) ? (w + 8 * j) : (32 + w);
            int c = t * 8 + 2 * (lane & 3);
            *(float2*)&dst[d0 * 276 + c]       = make_float2(acc[mt][j][0], acc[mt][j][1]);
            *(float2*)&dst[(d0 + 8) * 276 + c] = make_float2(acc[mt][j][2], acc[mt][j][3]);
        }
    }
}

__global__ __launch_bounds__(256) void kv_reduce_kernel(
    const float* __restrict__ kvpart, float* __restrict__ kvT)
{
    int idx = blockIdx.x * 256 + threadIdx.x;
    const int total = 64 * 80 * 276;
    if (idx < total) {
        float s = kvpart[idx] + kvpart[total + idx]
                + kvpart[2 * total + idx] + kvpart[3 * total + idx];
        kvT[idx] = s;
    }
}

// ---------------- ctx as TF32 MMA with fused denom -----------------------------
// per (bh, 128-l tile): D[l][n] = sum_m qp[l][m] * kvT[n][m], n: 64 d's + denom@64
__global__ __launch_bounds__(256) void ctx_gemm_kernel(
    const float* __restrict__ qp, const float* __restrict__ kvT,
    float* __restrict__ ctx)
{
    extern __shared__ float sm[];
    float* kvs = sm;              // [80][276]
    float* As  = sm + 80 * 276;   // [128][20]

    int tid = threadIdx.x;
    int lane = tid & 31, w = tid >> 5;
    int bh = blockIdx.y;
    int b = bh >> 4, h = bh & 15;
    int lblk = blockIdx.x * 128;

    for (int idx = tid; idx < 80 * 69; idx += 256) {
        int d = idx / 69, q = idx % 69;
        float4 v = *(const float4*)&kvT[(size_t)bh * 80 * 276 + d * 276 + 4 * q];
        *(float4*)&kvs[d * 276 + 4 * q] = v;
    }

    float acc[9][4];
#pragma unroll
    for (int t = 0; t < 9; ++t)
#pragma unroll
        for (int i = 0; i < 4; ++i) acc[t][i] = 0.f;

    int r = lane >> 2;
    int arow = w * 16 + r;

    for (int ch = 0; ch < 17; ++ch) {
        __syncthreads();
        for (int idx = tid; idx < 512; idx += 256) {
            int rr = idx >> 2, q = (idx & 3) * 4;
            float4 v = *(const float4*)&qp[((size_t)bh * LL + lblk + rr) * MP + ch * 16 + q];
            *(float4*)&As[rr * 20 + q] = v;
        }
        __syncthreads();

#pragma unroll
        for (int ks = 0; ks < 2; ++ks) {
            int kk = ks * 8 + (lane & 3);
            uint32_t a[4];
            a[0] = cvt_tf32(As[arow * 20 + kk]);
            a[1] = cvt_tf32(As[(arow + 8) * 20 + kk]);
            a[2] = cvt_tf32(As[arow * 20 + kk + 4]);
            a[3] = cvt_tf32(As[(arow + 8) * 20 + kk + 4]);
            int kg = ch * 16 + kk;
#pragma unroll
            for (int t = 0; t < 9; ++t) {
                uint32_t bfr[2];
                int br = t * 8 + r;
                bfr[0] = cvt_tf32(kvs[br * 276 + kg]);
                bfr[1] = cvt_tf32(kvs[br * 276 + kg + 4]);
                mma_tf32(acc[t], a, bfr);
            }
        }
    }

    // denom: n-tile 8, col 64 -> held by lanes with (lane&3)==0
    float den0 = __shfl_sync(0xffffffffu, acc[8][0], lane & ~3);
    float den1 = __shfl_sync(0xffffffffu, acc[8][2], lane & ~3);
    float inv0 = 1.0f / (den0 + 1e-6f);
    float inv1 = 1.0f / (den1 + 1e-6f);

    int lrow0 = lblk + arow, lrow1 = lblk + arow + 8;
    float* o0 = ctx + ((size_t)(b * LL + lrow0)) * DD + h * DH;
    float* o1 = ctx + ((size_t)(b * LL + lrow1)) * DD + h * DH;
#pragma unroll
    for (int t = 0; t < 8; ++t) {
        int c = t * 8 + 2 * (lane & 3);
        *(float2*)&o0[c] = make_float2(acc[t][0] * inv0, acc[t][1] * inv0);
        *(float2*)&o1[c] = make_float2(acc[t][2] * inv1, acc[t][3] * inv1);
    }
}

// ---------------- host launcher ------------------------------------------------
extern "C" void kernel_launch(void* const* d_in, const int* in_sizes, int n_in,
                              void* d_out, int out_size)
{
    const float* query = (const float*)d_in[0];
    const float* key   = (const float*)d_in[1];
    const float* value = (const float*)d_in[2];
    const float* q_w   = (const float*)d_in[3];
    const float* q_b   = (const float*)d_in[4];
    const float* k_w   = (const float*)d_in[5];
    const float* k_b   = (const float*)d_in[6];
    const float* v_w   = (const float*)d_in[7];
    const float* v_b   = (const float*)d_in[8];
    const float* out_w = (const float*)d_in[9];
    const float* out_b = (const float*)d_in[10];
    const float* rf    = (const float*)d_in[11];
    float* out = (float*)d_out;

    float *p_qproj, *p_kproj, *p_vproj, *p_qp, *p_kp, *p_kvpart, *p_kvT, *p_ctx;
    cudaGetSymbolAddress((void**)&p_qproj, g_qproj);
    cudaGetSymbolAddress((void**)&p_kproj, g_kproj);
    cudaGetSymbolAddress((void**)&p_vproj, g_vproj);
    cudaGetSymbolAddress((void**)&p_qp, g_qp);
    cudaGetSymbolAddress((void**)&p_kp, g_kp);
    cudaGetSymbolAddress((void**)&p_kvpart, g_kvpart);
    cudaGetSymbolAddress((void**)&p_kvT, g_kvT);
    cudaGetSymbolAddress((void**)&p_ctx, g_ctx);

    int phi_smem = (272 * 68 + 128 * 68 + 128) * sizeof(float);   // 109,312 B
    int ctx_smem = (80 * 276 + 128 * 20) * sizeof(float);         //  98,560 B
    cudaFuncSetAttribute(phi_gemm_kernel, cudaFuncAttributeMaxDynamicSharedMemorySize, phi_smem);
    cudaFuncSetAttribute(ctx_gemm_kernel, cudaFuncAttributeMaxDynamicSharedMemorySize, ctx_smem);

    dim3 gemmGrid(DD / 128, NROWS / 128);   // (8, 128)
    gemm_tf32_kernel<<<gemmGrid, 256>>>(query, q_w, q_b, p_qproj, QK_SCALE);
    gemm_tf32_kernel<<<gemmGrid, 256>>>(key,   k_w, k_b, p_kproj, QK_SCALE);
    gemm_tf32_kernel<<<gemmGrid, 256>>>(value, v_w, v_b, p_vproj, 1.0f);

    phi_gemm_kernel<<<GROWS / 128, 256, phi_smem>>>(p_qproj, rf, p_qp);
    phi_gemm_kernel<<<GROWS / 128, 256, phi_smem>>>(p_kproj, rf, p_kp);

    dim3 kvGrid(4, BB * HH);                // (4 ksplit, 64 bh)
    kv_gemm_kernel<<<kvGrid, 256>>>(p_kp, p_vproj, p_kvpart);
    kv_reduce_kernel<<<(64 * 80 * 276 + 255) / 256, 256>>>(p_kvpart, p_kvT);

    dim3 ctxGrid(LL / 128, BB * HH);        // (32, 64)
    ctx_gemm_kernel<<<ctxGrid, 256, ctx_smem>>>(p_qp, p_kvT, p_ctx);

    gemm_tf32_kernel<<<gemmGrid, 256>>>(p_ctx, out_w, out_b, out, 1.0f);
}

// round 7
// speedup vs baseline: 4.2670x; 1.0049x over previous
#include <cuda_runtime.h>
#include <math.h>
#include <stdint.h>

// Problem constants
#define BB 4
#define LL 4096
#define DD 1024
#define HH 16
#define DH 64
#define MM 266
#define MP 272                 // M padded to 272 (34 n8-tiles)

#define NROWS (BB*LL)          // 16384
#define GROWS (BB*LL*HH)       // 262144 (b,l,h) rows
#define QK_SCALE 0.1767766952966369f   // 1/1024^0.25
#define PHI_SCALE 0.06131393394849658f // 1/sqrt(266)

// ---------------- scratch (device globals; no allocation allowed) -------------
__device__ float g_qr[NROWS*DD];       // tf32-rounded inputs
__device__ float g_kr[NROWS*DD];
__device__ float g_vr[NROWS*DD];
__device__ float g_wq[DD*DD];
__device__ float g_wk[DD*DD];
__device__ float g_wv[DD*DD];
__device__ float g_wo[DD*DD];
__device__ float g_qproj[NROWS*DD];
__device__ float g_kproj[NROWS*DD];
__device__ float g_vproj[NROWS*DD];
__device__ float g_qp[(size_t)BB*HH*LL*MP];     // (bh, l, 272) tf32-rounded
__device__ float g_kp[(size_t)BB*HH*LL*MP];
__device__ float g_kvpart[4*BB*HH*80*276];      // k-split partials of kvT
__device__ float g_kvT[BB*HH*80*276];           // kvT[bh][d(80)][m(276)], row64=ksum
__device__ float g_ctx[NROWS*DD];

// ---------------- common helpers -----------------------------------------------
__device__ __forceinline__ uint32_t cvt_tf32(float x) {
    uint32_t r;
    asm("cvt.rna.tf32.f32 %0, %1;" : "=r"(r) : "f"(x));
    return r;
}
__device__ __forceinline__ float rnd_tf32(float x) {
    return __uint_as_float(cvt_tf32(x));
}
__device__ __forceinline__ void cp16(uint32_t s, const void* g) {
    asm volatile("cp.async.cg.shared.global [%0], [%1], 16;" :: "r"(s), "l"(g));
}
__device__ __forceinline__ void cp_commit() {
    asm volatile("cp.async.commit_group;");
}
template<int N> __device__ __forceinline__ void cp_wait() {
    asm volatile("cp.async.wait_group %0;" :: "n"(N));
}
__device__ __forceinline__ void mma_tf32(float* c, const uint32_t* a, const uint32_t* b) {
    asm volatile(
        "mma.sync.aligned.m16n8k8.row.col.f32.tf32.tf32.f32 "
        "{%0,%1,%2,%3},{%4,%5,%6,%7},{%8,%9},{%0,%1,%2,%3};"
        : "+f"(c[0]), "+f"(c[1]), "+f"(c[2]), "+f"(c[3])
        : "r"(a[0]), "r"(a[1]), "r"(a[2]), "r"(a[3]), "r"(b[0]), "r"(b[1]));
}

// ---------------- pre-round inputs to tf32 --------------------------------------
__global__ __launch_bounds__(256) void round_tf32_kernel(
    const float4* __restrict__ src, float4* __restrict__ dst, int n4)
{
    int i = blockIdx.x * 256 + threadIdx.x;
    if (i < n4) {
        float4 v = src[i];
        v.x = rnd_tf32(v.x); v.y = rnd_tf32(v.y);
        v.z = rnd_tf32(v.z); v.w = rnd_tf32(v.w);
        dst[i] = v;
    }
}

// ---------------- TF32 tensor-core GEMM: Y = alpha * (X @ W^T + bias) ---------
// Inputs X, W are PRE-ROUNDED tf32; frags loaded raw. round_out rounds Y.
#define SMPAD 20

__global__ __launch_bounds__(256) void gemm_tf32_kernel(
    const float* __restrict__ X, const float* __restrict__ W,
    const float* __restrict__ bias, float* __restrict__ Y, float alpha,
    int round_out)
{
    __shared__ __align__(16) float As[2][128 * SMPAD];
    __shared__ __align__(16) float Bs[2][128 * SMPAD];

    int tid = threadIdx.x;
    int lane = tid & 31, warp = tid >> 5;
    int wm = warp >> 2, wn = warp & 3;
    int rowBase = blockIdx.y * 128, colBase = blockIdx.x * 128;

    int f0 = tid * 2;
    int lr0 = f0 >> 2,      lc0 = (f0 & 3) * 4;
    int lr1 = (f0 + 1) >> 2, lc1 = ((f0 + 1) & 3) * 4;

    const float* gA0 = X + (size_t)(rowBase + lr0) * DD + lc0;
    const float* gA1 = X + (size_t)(rowBase + lr1) * DD + lc1;
    const float* gB0 = W + (size_t)(colBase + lr0) * DD + lc0;
    const float* gB1 = W + (size_t)(colBase + lr1) * DD + lc1;

    uint32_t sA0[2], sA1[2], sB0[2], sB1[2];
#pragma unroll
    for (int b = 0; b < 2; ++b) {
        sA0[b] = (uint32_t)__cvta_generic_to_shared(&As[b][lr0 * SMPAD + lc0]);
        sA1[b] = (uint32_t)__cvta_generic_to_shared(&As[b][lr1 * SMPAD + lc1]);
        sB0[b] = (uint32_t)__cvta_generic_to_shared(&Bs[b][lr0 * SMPAD + lc0]);
        sB1[b] = (uint32_t)__cvta_generic_to_shared(&Bs[b][lr1 * SMPAD + lc1]);
    }

    float acc[4][4][4];
#pragma unroll
    for (int mt = 0; mt < 4; ++mt)
#pragma unroll
        for (int nt = 0; nt < 4; ++nt)
#pragma unroll
            for (int i = 0; i < 4; ++i) acc[mt][nt][i] = 0.f;

    cp16(sA0[0], gA0); cp16(sA1[0], gA1);
    cp16(sB0[0], gB0); cp16(sB1[0], gB1);
    cp_commit();

    const int NK = DD / 16;
    for (int kt = 0; kt < NK; ++kt) {
        int buf = kt & 1;
        if (kt + 1 < NK) {
            int off = (kt + 1) * 16;
            cp16(sA0[buf ^ 1], gA0 + off); cp16(sA1[buf ^ 1], gA1 + off);
            cp16(sB0[buf ^ 1], gB0 + off); cp16(sB1[buf ^ 1], gB1 + off);
            cp_commit();
            cp_wait<1>();
        } else {
            cp_wait<0>();
        }
        __syncthreads();

#pragma unroll
        for (int ks = 0; ks < 2; ++ks) {
            int kk = ks * 8 + (lane & 3);
            int r = lane >> 2;
            uint32_t a[4][4], b[4][2];
#pragma unroll
            for (int mt = 0; mt < 4; ++mt) {
                int ar = wm * 64 + mt * 16 + r;
                a[mt][0] = __float_as_uint(As[buf][ar * SMPAD + kk]);
                a[mt][1] = __float_as_uint(As[buf][(ar + 8) * SMPAD + kk]);
                a[mt][2] = __float_as_uint(As[buf][ar * SMPAD + kk + 4]);
                a[mt][3] = __float_as_uint(As[buf][(ar + 8) * SMPAD + kk + 4]);
            }
#pragma unroll
            for (int nt = 0; nt < 4; ++nt) {
                int br = wn * 32 + nt * 8 + r;
                b[nt][0] = __float_as_uint(Bs[buf][br * SMPAD + kk]);
                b[nt][1] = __float_as_uint(Bs[buf][br * SMPAD + kk + 4]);
            }
#pragma unroll
            for (int mt = 0; mt < 4; ++mt)
#pragma unroll
                for (int nt = 0; nt < 4; ++nt)
                    mma_tf32(acc[mt][nt], a[mt], b[nt]);
        }
        __syncthreads();
    }

#pragma unroll
    for (int mt = 0; mt < 4; ++mt) {
        int r0 = rowBase + wm * 64 + mt * 16 + (lane >> 2);
#pragma unroll
        for (int nt = 0; nt < 4; ++nt) {
            int c = colBase + wn * 32 + nt * 8 + 2 * (lane & 3);
            float2 bv = *(const float2*)&bias[c];
            float2 o0, o1;
            o0.x = alpha * (acc[mt][nt][0] + bv.x);
            o0.y = alpha * (acc[mt][nt][1] + bv.y);
            o1.x = alpha * (acc[mt][nt][2] + bv.x);
            o1.y = alpha * (acc[mt][nt][3] + bv.y);
            if (round_out) {
                o0.x = rnd_tf32(o0.x); o0.y = rnd_tf32(o0.y);
                o1.x = rnd_tf32(o1.x); o1.y = rnd_tf32(o1.y);
            }
            *(float2*)&Y[(size_t)r0 * DD + c] = o0;
            *(float2*)&Y[(size_t)(r0 + 8) * DD + c] = o1;
        }
    }
}

// ---------------- phi as TF32 MMA GEMM + fused max/exp -------------------------
// A (proj rows) register-resident; rf in smem (rounded). Output rounded tf32.
__global__ __launch_bounds__(256) void phi_gemm_kernel(
    const float* __restrict__ proj, const float* __restrict__ rf,
    float* __restrict__ out)
{
    extern __shared__ float rfs[];   // [272][68]

    int tid = threadIdx.x;
    int lane = tid & 31, w = tid >> 5;
    int g0 = blockIdx.x * 128;

    for (int idx = tid; idx < 266 * 16; idx += 256) {
        int m = idx >> 4, q = (idx & 15) * 4;
        float4 v = *(const float4*)&rf[m * 64 + q];
        rfs[m * 68 + q + 0] = rnd_tf32(v.x);
        rfs[m * 68 + q + 1] = rnd_tf32(v.y);
        rfs[m * 68 + q + 2] = rnd_tf32(v.z);
        rfs[m * 68 + q + 3] = rnd_tf32(v.w);
    }
    for (int idx = tid; idx < 6 * 64; idx += 256) {
        int m = 266 + idx / 64, d = idx % 64;
        rfs[m * 68 + d] = 0.f;
    }

    int c = lane & 3, r = lane >> 2;
    int arow = w * 16 + r;
    int row0 = g0 + arow, row1 = row0 + 8;

    // register-resident A rows (already tf32-rounded by producer)
    float x0[16], x1[16];
    const float* p0 = proj + (size_t)row0 * 64 + c;
    const float* p1 = proj + (size_t)row1 * 64 + c;
#pragma unroll
    for (int j = 0; j < 16; ++j) { x0[j] = p0[4 * j]; x1[j] = p1[4 * j]; }

    // h = -||x||^2/2 via quad reduction (c=0..3 hold disjoint col sets)
    float s0 = 0.f, s1 = 0.f;
#pragma unroll
    for (int j = 0; j < 16; ++j) { s0 += x0[j] * x0[j]; s1 += x1[j] * x1[j]; }
    s0 += __shfl_xor_sync(0xffffffffu, s0, 1);
    s0 += __shfl_xor_sync(0xffffffffu, s0, 2);
    s1 += __shfl_xor_sync(0xffffffffu, s1, 1);
    s1 += __shfl_xor_sync(0xffffffffu, s1, 2);
    float h0 = -0.5f * s0, h1 = -0.5f * s1;

    __syncthreads();

    float acc[34][4];
#pragma unroll
    for (int t = 0; t < 34; ++t)
#pragma unroll
        for (int i = 0; i < 4; ++i) acc[t][i] = 0.f;

#pragma unroll
    for (int ks = 0; ks < 8; ++ks) {
        int kk = ks * 8 + c;
        uint32_t a[4];
        a[0] = __float_as_uint(x0[2 * ks]);
        a[1] = __float_as_uint(x1[2 * ks]);
        a[2] = __float_as_uint(x0[2 * ks + 1]);
        a[3] = __float_as_uint(x1[2 * ks + 1]);
#pragma unroll
        for (int t = 0; t < 34; ++t) {
            uint32_t b[2];
            int br = t * 8 + r;
            b[0] = __float_as_uint(rfs[br * 68 + kk]);
            b[1] = __float_as_uint(rfs[br * 68 + kk + 4]);
            mma_tf32(acc[t], a, b);
        }
    }

    // row max over real 266 cols
    float mx0 = -3.0e38f, mx1 = -3.0e38f;
#pragma unroll
    for (int t = 0; t < 34; ++t) {
        int c0 = t * 8 + 2 * c;
        if (c0 < 266)     { mx0 = fmaxf(mx0, acc[t][0]); mx1 = fmaxf(mx1, acc[t][2]); }
        if (c0 + 1 < 266) { mx0 = fmaxf(mx0, acc[t][1]); mx1 = fmaxf(mx1, acc[t][3]); }
    }
    mx0 = fmaxf(mx0, __shfl_xor_sync(0xffffffffu, mx0, 1));
    mx0 = fmaxf(mx0, __shfl_xor_sync(0xffffffffu, mx0, 2));
    mx1 = fmaxf(mx1, __shfl_xor_sync(0xffffffffu, mx1, 1));
    mx1 = fmaxf(mx1, __shfl_xor_sync(0xffffffffu, mx1, 2));

    int b0i = row0 >> 16, rem0 = row0 & 65535, l0 = rem0 >> 4, hh0 = rem0 & 15;
    int b1i = row1 >> 16, rem1 = row1 & 65535, l1 = rem1 >> 4, hh1 = rem1 & 15;
    float* d0p = out + ((size_t)(b0i * 16 + hh0) * LL + l0) * MP;
    float* d1p = out + ((size_t)(b1i * 16 + hh1) * LL + l1) * MP;

#pragma unroll
    for (int t = 0; t < 34; ++t) {
        int c0 = t * 8 + 2 * c;
        float2 v0, v1;
        v0.x = (c0     < 266) ? rnd_tf32(__expf(h0 + acc[t][0] - mx0) * PHI_SCALE) : 0.f;
        v0.y = (c0 + 1 < 266) ? rnd_tf32(__expf(h0 + acc[t][1] - mx0) * PHI_SCALE) : 0.f;
        v1.x = (c0     < 266) ? rnd_tf32(__expf(h1 + acc[t][2] - mx1) * PHI_SCALE) : 0.f;
        v1.y = (c0 + 1 < 266) ? rnd_tf32(__expf(h1 + acc[t][3] - mx1) * PHI_SCALE) : 0.f;
        *(float2*)&d0p[c0] = v0;
        *(float2*)&d1p[c0] = v1;
    }
}

// ---------------- kv as TF32 MMA: kvT[d][m] = sum_l vT[d][l]*kp[l][m] ----------
__global__ __launch_bounds__(256) void kv_gemm_kernel(
    const float* __restrict__ kp, const float* __restrict__ vproj,
    float* __restrict__ kvpart)
{
    __shared__ float kps[32 * 272];   // [l][m] (rounded at producer)
    __shared__ float vsT[80 * 36];    // [d][l] (rounded), row64=1, 65..79=0

    int tid = threadIdx.x;
    int lane = tid & 31, w = tid >> 5;
    int split = blockIdx.x, bh = blockIdx.y;
    int b = bh >> 4, h = bh & 15;

    for (int idx = tid; idx < 16 * 36; idx += 256)
        vsT[64 * 36 + idx] = (idx < 32) ? 1.0f : 0.f;

    int ntiles = (w < 2) ? 5 : 4;
    float acc[5][5][4];
#pragma unroll
    for (int mt = 0; mt < 5; ++mt)
#pragma unroll
        for (int j = 0; j < 5; ++j)
#pragma unroll
            for (int i = 0; i < 4; ++i) acc[mt][j][i] = 0.f;

    int lbase = split * 1024;
    for (int ch = 0; ch < 32; ++ch) {
        int l0 = lbase + ch * 32;
        __syncthreads();
        for (int idx = tid; idx < 32 * 68; idx += 256) {
            int m4 = idx % 68, l = idx / 68;
            float4 v = *(const float4*)&kp[((size_t)bh * LL + l0 + l) * MP + 4 * m4];
            *(float4*)&kps[l * 272 + 4 * m4] = v;
        }
        for (int idx = tid; idx < 512; idx += 256) {
            int d4 = idx & 15, l = idx >> 4;
            float4 v = *(const float4*)&vproj[((size_t)(b * LL + l0 + l)) * DD + h * DH + 4 * d4];
            vsT[(4 * d4 + 0) * 36 + l] = v.x;
            vsT[(4 * d4 + 1) * 36 + l] = v.y;
            vsT[(4 * d4 + 2) * 36 + l] = v.z;
            vsT[(4 * d4 + 3) * 36 + l] = v.w;
        }
        __syncthreads();

#pragma unroll
        for (int ks = 0; ks < 4; ++ks) {
            int kk = ks * 8 + (lane & 3);
            int r = lane >> 2;
            uint32_t a[5][4];
#pragma unroll
            for (int mt = 0; mt < 5; ++mt) {
                int ar = mt * 16 + r;
                a[mt][0] = __float_as_uint(vsT[ar * 36 + kk]);
                a[mt][1] = __float_as_uint(vsT[(ar + 8) * 36 + kk]);
                a[mt][2] = __float_as_uint(vsT[ar * 36 + kk + 4]);
                a[mt][3] = __float_as_uint(vsT[(ar + 8) * 36 + kk + 4]);
            }
#pragma unroll
            for (int j = 0; j < 5; ++j) {
                if (j >= ntiles) break;
                int t = (j < 4) ? (w + 8 * j) : (32 + w);
                uint32_t bfr[2];
                bfr[0] = __float_as_uint(kps[kk * 272 + t * 8 + r]);
                bfr[1] = __float_as_uint(kps[(kk + 4) * 272 + t * 8 + r]);
#pragma unroll
                for (int mt = 0; mt < 5; ++mt)
                    mma_tf32(acc[mt][j], a[mt], bfr);
            }
        }
    }

    float* dst = kvpart + (size_t)(split * 64 + bh) * 80 * 276;
#pragma unroll
    for (int mt = 0; mt < 5; ++mt) {
        int d0 = mt * 16 + (lane >> 2);
#pragma unroll
        for (int j = 0; j < 5; ++j) {
            if (j >= ntiles) break;
            int t = (j < 4) ? (w + 8 * j) : (32 + w);
            int c = t * 8 + 2 * (lane & 3);
            *(float2*)&dst[d0 * 276 + c]       = make_float2(acc[mt][j][0], acc[mt][j][1]);
            *(float2*)&dst[(d0 + 8) * 276 + c] = make_float2(acc[mt][j][2], acc[mt][j][3]);
        }
    }
}

__global__ __launch_bounds__(256) void kv_reduce_kernel(
    const float* __restrict__ kvpart, float* __restrict__ kvT)
{
    int idx = blockIdx.x * 256 + threadIdx.x;
    const int total = 64 * 80 * 276;
    if (idx < total) {
        float s = kvpart[idx] + kvpart[total + idx]
                + kvpart[2 * total + idx] + kvpart[3 * total + idx];
        kvT[idx] = rnd_tf32(s);
    }
}

// ---------------- ctx as TF32 MMA with fused denom -----------------------------
__global__ __launch_bounds__(256) void ctx_gemm_kernel(
    const float* __restrict__ qp, const float* __restrict__ kvT,
    float* __restrict__ ctx)
{
    extern __shared__ float sm[];
    float* kvs = sm;              // [80][276]
    float* As  = sm + 80 * 276;   // [128][20]

    int tid = threadIdx.x;
    int lane = tid & 31, w = tid >> 5;
    int bh = blockIdx.y;
    int b = bh >> 4, h = bh & 15;
    int lblk = blockIdx.x * 128;

    for (int idx = tid; idx < 80 * 69; idx += 256) {
        int d = idx / 69, q = idx % 69;
        float4 v = *(const float4*)&kvT[(size_t)bh * 80 * 276 + d * 276 + 4 * q];
        *(float4*)&kvs[d * 276 + 4 * q] = v;
    }

    float acc[9][4];
#pragma unroll
    for (int t = 0; t < 9; ++t)
#pragma unroll
        for (int i = 0; i < 4; ++i) acc[t][i] = 0.f;

    int r = lane >> 2;
    int arow = w * 16 + r;

    for (int ch = 0; ch < 17; ++ch) {
        __syncthreads();
        for (int idx = tid; idx < 512; idx += 256) {
            int rr = idx >> 2, q = (idx & 3) * 4;
            float4 v = *(const float4*)&qp[((size_t)bh * LL + lblk + rr) * MP + ch * 16 + q];
            *(float4*)&As[rr * 20 + q] = v;
        }
        __syncthreads();

#pragma unroll
        for (int ks = 0; ks < 2; ++ks) {
            int kk = ks * 8 + (lane & 3);
            uint32_t a[4];
            a[0] = __float_as_uint(As[arow * 20 + kk]);
            a[1] = __float_as_uint(As[(arow + 8) * 20 + kk]);
            a[2] = __float_as_uint(As[arow * 20 + kk + 4]);
            a[3] = __float_as_uint(As[(arow + 8) * 20 + kk + 4]);
            int kg = ch * 16 + kk;
#pragma unroll
            for (int t = 0; t < 9; ++t) {
                uint32_t bfr[2];
                int br = t * 8 + r;
                bfr[0] = __float_as_uint(kvs[br * 276 + kg]);
                bfr[1] = __float_as_uint(kvs[br * 276 + kg + 4]);
                mma_tf32(acc[t], a, bfr);
            }
        }
    }

    float den0 = __shfl_sync(0xffffffffu, acc[8][0], lane & ~3);
    float den1 = __shfl_sync(0xffffffffu, acc[8][2], lane & ~3);
    float inv0 = 1.0f / (den0 + 1e-6f);
    float inv1 = 1.0f / (den1 + 1e-6f);

    int lrow0 = lblk + arow, lrow1 = lblk + arow + 8;
    float* o0 = ctx + ((size_t)(b * LL + lrow0)) * DD + h * DH;
    float* o1 = ctx + ((size_t)(b * LL + lrow1)) * DD + h * DH;
#pragma unroll
    for (int t = 0; t < 8; ++t) {
        int c = t * 8 + 2 * (lane & 3);
        *(float2*)&o0[c] = make_float2(rnd_tf32(acc[t][0] * inv0), rnd_tf32(acc[t][1] * inv0));
        *(float2*)&o1[c] = make_float2(rnd_tf32(acc[t][2] * inv1), rnd_tf32(acc[t][3] * inv1));
    }
}

// ---------------- host launcher ------------------------------------------------
extern "C" void kernel_launch(void* const* d_in, const int* in_sizes, int n_in,
                              void* d_out, int out_size)
{
    const float* query = (const float*)d_in[0];
    const float* key   = (const float*)d_in[1];
    const float* value = (const float*)d_in[2];
    const float* q_w   = (const float*)d_in[3];
    const float* q_b   = (const float*)d_in[4];
    const float* k_w   = (const float*)d_in[5];
    const float* k_b   = (const float*)d_in[6];
    const float* v_w   = (const float*)d_in[7];
    const float* v_b   = (const float*)d_in[8];
    const float* out_w = (const float*)d_in[9];
    const float* out_b = (const float*)d_in[10];
    const float* rf    = (const float*)d_in[11];
    float* out = (float*)d_out;

    float *p_qr, *p_kr, *p_vr, *p_wq, *p_wk, *p_wv, *p_wo;
    float *p_qproj, *p_kproj, *p_vproj, *p_qp, *p_kp, *p_kvpart, *p_kvT, *p_ctx;
    cudaGetSymbolAddress((void**)&p_qr, g_qr);
    cudaGetSymbolAddress((void**)&p_kr, g_kr);
    cudaGetSymbolAddress((void**)&p_vr, g_vr);
    cudaGetSymbolAddress((void**)&p_wq, g_wq);
    cudaGetSymbolAddress((void**)&p_wk, g_wk);
    cudaGetSymbolAddress((void**)&p_wv, g_wv);
    cudaGetSymbolAddress((void**)&p_wo, g_wo);
    cudaGetSymbolAddress((void**)&p_qproj, g_qproj);
    cudaGetSymbolAddress((void**)&p_kproj, g_kproj);
    cudaGetSymbolAddress((void**)&p_vproj, g_vproj);
    cudaGetSymbolAddress((void**)&p_qp, g_qp);
    cudaGetSymbolAddress((void**)&p_kp, g_kp);
    cudaGetSymbolAddress((void**)&p_kvpart, g_kvpart);
    cudaGetSymbolAddress((void**)&p_kvT, g_kvT);
    cudaGetSymbolAddress((void**)&p_ctx, g_ctx);

    int phi_smem = 272 * 68 * sizeof(float);                 // 73,984 B -> 2 blocks/SM
    int ctx_smem = (80 * 276 + 128 * 20) * sizeof(float);    // 98,560 B
    cudaFuncSetAttribute(phi_gemm_kernel, cudaFuncAttributeMaxDynamicSharedMemorySize, phi_smem);
    cudaFuncSetAttribute(ctx_gemm_kernel, cudaFuncAttributeMaxDynamicSharedMemorySize, ctx_smem);

    // pre-round inputs to tf32 (memory-bound, ~55us total)
    const int NB = NROWS * DD / 4;   // 4M float4
    const int WB = DD * DD / 4;      // 256K float4
    round_tf32_kernel<<<(NB + 255) / 256, 256>>>((const float4*)query, (float4*)p_qr, NB);
    round_tf32_kernel<<<(NB + 255) / 256, 256>>>((const float4*)key,   (float4*)p_kr, NB);
    round_tf32_kernel<<<(NB + 255) / 256, 256>>>((const float4*)value, (float4*)p_vr, NB);
    round_tf32_kernel<<<(WB + 255) / 256, 256>>>((const float4*)q_w,   (float4*)p_wq, WB);
    round_tf32_kernel<<<(WB + 255) / 256, 256>>>((const float4*)k_w,   (float4*)p_wk, WB);
    round_tf32_kernel<<<(WB + 255) / 256, 256>>>((const float4*)v_w,   (float4*)p_wv, WB);
    round_tf32_kernel<<<(WB + 255) / 256, 256>>>((const float4*)out_w, (float4*)p_wo, WB);

    dim3 gemmGrid(DD / 128, NROWS / 128);   // (8, 128)
    gemm_tf32_kernel<<<gemmGrid, 256>>>(p_qr, p_wq, q_b, p_qproj, QK_SCALE, 1);
    gemm_tf32_kernel<<<gemmGrid, 256>>>(p_kr, p_wk, k_b, p_kproj, QK_SCALE, 1);
    gemm_tf32_kernel<<<gemmGrid, 256>>>(p_vr, p_wv, v_b, p_vproj, 1.0f, 1);

    phi_gemm_kernel<<<GROWS / 128, 256, phi_smem>>>(p_qproj, rf, p_qp);
    phi_gemm_kernel<<<GROWS / 128, 256, phi_smem>>>(p_kproj, rf, p_kp);

    dim3 kvGrid(4, BB * HH);                // (4 ksplit, 64 bh)
    kv_gemm_kernel<<<kvGrid, 256>>>(p_kp, p_vproj, p_kvpart);
    kv_reduce_kernel<<<(64 * 80 * 276 + 255) / 256, 256>>>(p_kvpart, p_kvT);

    dim3 ctxGrid(LL / 128, BB * HH);        // (32, 64)
    ctx_gemm_kernel<<<ctxGrid, 256, ctx_smem>>>(p_qp, p_kvT, p_ctx);

    gemm_tf32_kernel<<<gemmGrid, 256>>>(p_ctx, p_wo, out_b, out, 1.0f, 0);
}

// round 10
// speedup vs baseline: 5.3504x; 1.2539x over previous
#include <cuda_runtime.h>
#include <cuda_fp16.h>
#include <math.h>
#include <stdint.h>

// Problem constants
#define BB 4
#define LL 4096
#define DD 1024
#define HH 16
#define DH 64
#define MM 266
#define MP 272                 // M padded to 272 (34 n8-tiles)

#define NROWS (BB*LL)          // 16384
#define GROWS (BB*LL*HH)       // 262144 (b,l,h) rows
#define QK_SCALE 0.1767766952966369f   // 1/1024^0.25
#define PHI_SCALE 0.06131393394849658f // 1/sqrt(266)

// ---------------- scratch (device globals; no allocation allowed) -------------
__device__ __half g_qh[NROWS*DD];      // fp16 inputs
__device__ __half g_kh[NROWS*DD];
__device__ __half g_vh[NROWS*DD];
__device__ __half g_wqh[DD*DD];
__device__ __half g_wkh[DD*DD];
__device__ __half g_wvh[DD*DD];
__device__ __half g_woh[DD*DD];
__device__ __half g_ctxh[NROWS*DD];
__device__ float g_qproj[NROWS*DD];    // fp32 (tf32-rounded) projections
__device__ float g_kproj[NROWS*DD];
__device__ float g_vproj[NROWS*DD];
__device__ float g_qp[(size_t)BB*HH*LL*MP];     // (bh, l, 272) tf32-rounded
__device__ float g_kp[(size_t)BB*HH*LL*MP];
__device__ float g_kvpart[4*BB*HH*80*276];      // k-split partials of kvT
__device__ float g_kvT[BB*HH*80*276];           // kvT[bh][d(80)][m(276)], row64=ksum
__device__ float g_denom_unused[1];

// ---------------- common helpers -----------------------------------------------
__device__ __forceinline__ uint32_t cvt_tf32(float x) {
    uint32_t r;
    asm("cvt.rna.tf32.f32 %0, %1;" : "=r"(r) : "f"(x));
    return r;
}
__device__ __forceinline__ float rnd_tf32(float x) {
    return __uint_as_float(cvt_tf32(x));
}
__device__ __forceinline__ void cp16(uint32_t s, const void* g) {
    asm volatile("cp.async.cg.shared.global [%0], [%1], 16;" :: "r"(s), "l"(g));
}
__device__ __forceinline__ void cp_commit() {
    asm volatile("cp.async.commit_group;");
}
template<int N> __device__ __forceinline__ void cp_wait() {
    asm volatile("cp.async.wait_group %0;" :: "n"(N));
}
__device__ __forceinline__ void mma_tf32(float* c, const uint32_t* a, const uint32_t* b) {
    asm volatile(
        "mma.sync.aligned.m16n8k8.row.col.f32.tf32.tf32.f32 "
        "{%0,%1,%2,%3},{%4,%5,%6,%7},{%8,%9},{%0,%1,%2,%3};"
        : "+f"(c[0]), "+f"(c[1]), "+f"(c[2]), "+f"(c[3])
        : "r"(a[0]), "r"(a[1]), "r"(a[2]), "r"(a[3]), "r"(b[0]), "r"(b[1]));
}
__device__ __forceinline__ void mma_f16(float* c, const uint32_t* a, const uint32_t* b) {
    asm volatile(
        "mma.sync.aligned.m16n8k16.row.col.f32.f16.f16.f32 "
        "{%0,%1,%2,%3},{%4,%5,%6,%7},{%8,%9},{%0,%1,%2,%3};"
        : "+f"(c[0]), "+f"(c[1]), "+f"(c[2]), "+f"(c[3])
        : "r"(a[0]), "r"(a[1]), "r"(a[2]), "r"(a[3]), "r"(b[0]), "r"(b[1]));
}

// ---------------- fp32 -> fp16 conversion ---------------------------------------
__global__ __launch_bounds__(256) void f2h_kernel(
    const float4* __restrict__ src, __half2* __restrict__ dst, int n4)
{
    int i = blockIdx.x * 256 + threadIdx.x;
    if (i < n4) {
        float4 v = src[i];
        dst[2 * i + 0] = __floats2half2_rn(v.x, v.y);
        dst[2 * i + 1] = __floats2half2_rn(v.z, v.w);
    }
}

// ---------------- FP16 tensor-core GEMM: Y = alpha * (X @ W^T + bias) ----------
// X: (Nr,1024) row-major fp16, W: (1024,1024) row-major fp16, Y fp32.
// 128x128 tile, BK=64 halves (128B/row), double buffer, warp grid 2x4,
// warp tile 64x32 via m16n8k16. Row stride 72 halves (36 words == 4 mod 32).
#define SHH 72

__global__ __launch_bounds__(256) void gemm_fp16_kernel(
    const __half* __restrict__ X, const __half* __restrict__ W,
    const float* __restrict__ bias, float* __restrict__ Y,
    float alpha, int round_out)
{
    extern __shared__ __align__(16) __half hsm[];
    __half* Abuf[2] = { hsm,             hsm + 128 * SHH };
    __half* Bbuf[2] = { hsm + 2 * 128 * SHH, hsm + 3 * 128 * SHH };

    int tid = threadIdx.x;
    int lane = tid & 31, warp = tid >> 5;
    int wm = warp >> 2, wn = warp & 3;
    int rowBase = blockIdx.y * 128, colBase = blockIdx.x * 128;

    // loader: thread t -> row = t>>1, units j0..j0+3 (16B each, 8 units/row)
    int lrow = tid >> 1, j0 = (tid & 1) * 4;
    const __half* gA = X + (size_t)(rowBase + lrow) * DD + j0 * 8;
    const __half* gB = W + (size_t)(colBase + lrow) * DD + j0 * 8;
    uint32_t sA[2][4], sB[2][4];
#pragma unroll
    for (int b = 0; b < 2; ++b)
#pragma unroll
        for (int i = 0; i < 4; ++i) {
            sA[b][i] = (uint32_t)__cvta_generic_to_shared(Abuf[b] + lrow * SHH + (j0 + i) * 8);
            sB[b][i] = (uint32_t)__cvta_generic_to_shared(Bbuf[b] + lrow * SHH + (j0 + i) * 8);
        }

#define LOAD_CHUNK(ch, b) do { \
    const __half* _ga = gA + (ch) * 64; \
    const __half* _gb = gB + (ch) * 64; \
    cp16(sA[b][0], _ga + 0);  cp16(sA[b][1], _ga + 8); \
    cp16(sA[b][2], _ga + 16); cp16(sA[b][3], _ga + 24); \
    cp16(sB[b][0], _gb + 0);  cp16(sB[b][1], _gb + 8); \
    cp16(sB[b][2], _gb + 16); cp16(sB[b][3], _gb + 24); \
    cp_commit(); \
} while (0)

    float acc[4][4][4];
#pragma unroll
    for (int mt = 0; mt < 4; ++mt)
#pragma unroll
        for (int nt = 0; nt < 4; ++nt)
#pragma unroll
            for (int i = 0; i < 4; ++i) acc[mt][nt][i] = 0.f;

    LOAD_CHUNK(0, 0);

    int qd = lane & 3, r8 = lane >> 2;
    const int NCH = DD / 64;   // 16
    for (int kt = 0; kt < NCH; ++kt) {
        int buf = kt & 1;
        if (kt + 1 < NCH) {
            LOAD_CHUNK(kt + 1, buf ^ 1);
            cp_wait<1>();
        } else {
            cp_wait<0>();
        }
        __syncthreads();

        const __half* Ab = Abuf[buf];
        const __half* Bb = Bbuf[buf];
#pragma unroll
        for (int ks = 0; ks < 4; ++ks) {
            int kh = ks * 16 + 2 * qd;
            uint32_t a[4][4], b[4][2];
#pragma unroll
            for (int mt = 0; mt < 4; ++mt) {
                int ar = wm * 64 + mt * 16 + r8;
                a[mt][0] = *(const uint32_t*)(Ab + ar * SHH + kh);
                a[mt][1] = *(const uint32_t*)(Ab + (ar + 8) * SHH + kh);
                a[mt][2] = *(const uint32_t*)(Ab + ar * SHH + kh + 8);
                a[mt][3] = *(const uint32_t*)(Ab + (ar + 8) * SHH + kh + 8);
            }
#pragma unroll
            for (int nt = 0; nt < 4; ++nt) {
                int br = wn * 32 + nt * 8 + r8;
                b[nt][0] = *(const uint32_t*)(Bb + br * SHH + kh);
                b[nt][1] = *(const uint32_t*)(Bb + br * SHH + kh + 8);
            }
#pragma unroll
            for (int mt = 0; mt < 4; ++mt)
#pragma unroll
                for (int nt = 0; nt < 4; ++nt)
                    mma_f16(acc[mt][nt], a[mt], b[nt]);
        }
        __syncthreads();
    }

#pragma unroll
    for (int mt = 0; mt < 4; ++mt) {
        int r0 = rowBase + wm * 64 + mt * 16 + r8;
#pragma unroll
        for (int nt = 0; nt < 4; ++nt) {
            int c = colBase + wn * 32 + nt * 8 + 2 * qd;
            float2 bv = *(const float2*)&bias[c];
            float2 o0, o1;
            o0.x = alpha * (acc[mt][nt][0] + bv.x);
            o0.y = alpha * (acc[mt][nt][1] + bv.y);
            o1.x = alpha * (acc[mt][nt][2] + bv.x);
            o1.y = alpha * (acc[mt][nt][3] + bv.y);
            if (round_out) {
                o0.x = rnd_tf32(o0.x); o0.y = rnd_tf32(o0.y);
                o1.x = rnd_tf32(o1.x); o1.y = rnd_tf32(o1.y);
            }
            *(float2*)&Y[(size_t)r0 * DD + c] = o0;
            *(float2*)&Y[(size_t)(r0 + 8) * DD + c] = o1;
        }
    }
#undef LOAD_CHUNK
}

// ---------------- phi as TF32 MMA GEMM + fused max/exp -------------------------
__global__ __launch_bounds__(256) void phi_gemm_kernel(
    const float* __restrict__ proj, const float* __restrict__ rf,
    float* __restrict__ out)
{
    extern __shared__ float rfs[];   // [272][68]

    int tid = threadIdx.x;
    int lane = tid & 31, w = tid >> 5;
    int g0 = blockIdx.x * 128;

    for (int idx = tid; idx < 266 * 16; idx += 256) {
        int m = idx >> 4, q = (idx & 15) * 4;
        float4 v = *(const float4*)&rf[m * 64 + q];
        rfs[m * 68 + q + 0] = rnd_tf32(v.x);
        rfs[m * 68 + q + 1] = rnd_tf32(v.y);
        rfs[m * 68 + q + 2] = rnd_tf32(v.z);
        rfs[m * 68 + q + 3] = rnd_tf32(v.w);
    }
    for (int idx = tid; idx < 6 * 64; idx += 256) {
        int m = 266 + idx / 64, d = idx % 64;
        rfs[m * 68 + d] = 0.f;
    }

    int c = lane & 3, r = lane >> 2;
    int arow = w * 16 + r;
    int row0 = g0 + arow, row1 = row0 + 8;

    float x0[16], x1[16];
    const float* p0 = proj + (size_t)row0 * 64 + c;
    const float* p1 = proj + (size_t)row1 * 64 + c;
#pragma unroll
    for (int j = 0; j < 16; ++j) { x0[j] = p0[4 * j]; x1[j] = p1[4 * j]; }

    float s0 = 0.f, s1 = 0.f;
#pragma unroll
    for (int j = 0; j < 16; ++j) { s0 += x0[j] * x0[j]; s1 += x1[j] * x1[j]; }
    s0 += __shfl_xor_sync(0xffffffffu, s0, 1);
    s0 += __shfl_xor_sync(0xffffffffu, s0, 2);
    s1 += __shfl_xor_sync(0xffffffffu, s1, 1);
    s1 += __shfl_xor_sync(0xffffffffu, s1, 2);
    float h0 = -0.5f * s0, h1 = -0.5f * s1;

    __syncthreads();

    float acc[34][4];
#pragma unroll
    for (int t = 0; t < 34; ++t)
#pragma unroll
        for (int i = 0; i < 4; ++i) acc[t][i] = 0.f;

#pragma unroll
    for (int ks = 0; ks < 8; ++ks) {
        int kk = ks * 8 + c;
        uint32_t a[4];
        a[0] = __float_as_uint(x0[2 * ks]);
        a[1] = __float_as_uint(x1[2 * ks]);
        a[2] = __float_as_uint(x0[2 * ks + 1]);
        a[3] = __float_as_uint(x1[2 * ks + 1]);
#pragma unroll
        for (int t = 0; t < 34; ++t) {
            uint32_t b[2];
            int br = t * 8 + r;
            b[0] = __float_as_uint(rfs[br * 68 + kk]);
            b[1] = __float_as_uint(rfs[br * 68 + kk + 4]);
            mma_tf32(acc[t], a, b);
        }
    }

    float mx0 = -3.0e38f, mx1 = -3.0e38f;
#pragma unroll
    for (int t = 0; t < 34; ++t) {
        int c0 = t * 8 + 2 * c;
        if (c0 < 266)     { mx0 = fmaxf(mx0, acc[t][0]); mx1 = fmaxf(mx1, acc[t][2]); }
        if (c0 + 1 < 266) { mx0 = fmaxf(mx0, acc[t][1]); mx1 = fmaxf(mx1, acc[t][3]); }
    }
    mx0 = fmaxf(mx0, __shfl_xor_sync(0xffffffffu, mx0, 1));
    mx0 = fmaxf(mx0, __shfl_xor_sync(0xffffffffu, mx0, 2));
    mx1 = fmaxf(mx1, __shfl_xor_sync(0xffffffffu, mx1, 1));
    mx1 = fmaxf(mx1, __shfl_xor_sync(0xffffffffu, mx1, 2));

    int b0i = row0 >> 16, rem0 = row0 & 65535, l0 = rem0 >> 4, hh0 = rem0 & 15;
    int b1i = row1 >> 16, rem1 = row1 & 65535, l1 = rem1 >> 4, hh1 = rem1 & 15;
    float* d0p = out + ((size_t)(b0i * 16 + hh0) * LL + l0) * MP;
    float* d1p = out + ((size_t)(b1i * 16 + hh1) * LL + l1) * MP;

#pragma unroll
    for (int t = 0; t < 34; ++t) {
        int c0 = t * 8 + 2 * c;
        float2 v0, v1;
        v0.x = (c0     < 266) ? rnd_tf32(__expf(h0 + acc[t][0] - mx0) * PHI_SCALE) : 0.f;
        v0.y = (c0 + 1 < 266) ? rnd_tf32(__expf(h0 + acc[t][1] - mx0) * PHI_SCALE) : 0.f;
        v1.x = (c0     < 266) ? rnd_tf32(__expf(h1 + acc[t][2] - mx1) * PHI_SCALE) : 0.f;
        v1.y = (c0 + 1 < 266) ? rnd_tf32(__expf(h1 + acc[t][3] - mx1) * PHI_SCALE) : 0.f;
        *(float2*)&d0p[c0] = v0;
        *(float2*)&d1p[c0] = v1;
    }
}

// ---------------- kv as TF32 MMA: kvT[d][m] = sum_l vT[d][l]*kp[l][m] ----------
__global__ __launch_bounds__(256) void kv_gemm_kernel(
    const float* __restrict__ kp, const float* __restrict__ vproj,
    float* __restrict__ kvpart)
{
    __shared__ float kps[32 * 272];
    __shared__ float vsT[80 * 36];

    int tid = threadIdx.x;
    int lane = tid & 31, w = tid >> 5;
    int split = blockIdx.x, bh = blockIdx.y;
    int b = bh >> 4, h = bh & 15;

    for (int idx = tid; idx < 16 * 36; idx += 256)
        vsT[64 * 36 + idx] = (idx < 32) ? 1.0f : 0.f;

    int ntiles = (w < 2) ? 5 : 4;
    float acc[5][5][4];
#pragma unroll
    for (int mt = 0; mt < 5; ++mt)
#pragma unroll
        for (int j = 0; j < 5; ++j)
#pragma unroll
            for (int i = 0; i < 4; ++i) acc[mt][j][i] = 0.f;

    int lbase = split * 1024;
    for (int ch = 0; ch < 32; ++ch) {
        int l0 = lbase + ch * 32;
        __syncthreads();
        for (int idx = tid; idx < 32 * 68; idx += 256) {
            int m4 = idx % 68, l = idx / 68;
            float4 v = *(const float4*)&kp[((size_t)bh * LL + l0 + l) * MP + 4 * m4];
            *(float4*)&kps[l * 272 + 4 * m4] = v;
        }
        for (int idx = tid; idx < 512; idx += 256) {
            int d4 = idx & 15, l = idx >> 4;
            float4 v = *(const float4*)&vproj[((size_t)(b * LL + l0 + l)) * DD + h * DH + 4 * d4];
            vsT[(4 * d4 + 0) * 36 + l] = v.x;
            vsT[(4 * d4 + 1) * 36 + l] = v.y;
            vsT[(4 * d4 + 2) * 36 + l] = v.z;
            vsT[(4 * d4 + 3) * 36 + l] = v.w;
        }
        __syncthreads();

#pragma unroll
        for (int ks = 0; ks < 4; ++ks) {
            int kk = ks * 8 + (lane & 3);
            int r = lane >> 2;
            uint32_t a[5][4];
#pragma unroll
            for (int mt = 0; mt < 5; ++mt) {
                int ar = mt * 16 + r;
                a[mt][0] = __float_as_uint(vsT[ar * 36 + kk]);
                a[mt][1] = __float_as_uint(vsT[(ar + 8) * 36 + kk]);
                a[mt][2] = __float_as_uint(vsT[ar * 36 + kk + 4]);
                a[mt][3] = __float_as_uint(vsT[(ar + 8) * 36 + kk + 4]);
            }
#pragma unroll
            for (int j = 0; j < 5; ++j) {
                if (j >= ntiles) break;
                int t = (j < 4) ? (w + 8 * j) : (32 + w);
                uint32_t bfr[2];
                bfr[0] = __float_as_uint(kps[kk * 272 + t * 8 + r]);
                bfr[1] = __float_as_uint(kps[(kk + 4) * 272 + t * 8 + r]);
#pragma unroll
                for (int mt = 0; mt < 5; ++mt)
                    mma_tf32(acc[mt][j], a[mt], bfr);
            }
        }
    }

    float* dst = kvpart + (size_t)(split * 64 + bh) * 80 * 276;
#pragma unroll
    for (int mt = 0; mt < 5; ++mt) {
        int d0 = mt * 16 + (lane >> 2);
#pragma unroll
        for (int j = 0; j < 5; ++j) {
            if (j >= ntiles) break;
            int t = (j < 4) ? (w + 8 * j) : (32 + w);
            int c = t * 8 + 2 * (lane & 3);
            *(float2*)&dst[d0 * 276 + c]       = make_float2(acc[mt][j][0], acc[mt][j][1]);
            *(float2*)&dst[(d0 + 8) * 276 + c] = make_float2(acc[mt][j][2], acc[mt][j][3]);
        }
    }
}

__global__ __launch_bounds__(256) void kv_reduce_kernel(
    const float* __restrict__ kvpart, float* __restrict__ kvT)
{
    int idx = blockIdx.x * 256 + threadIdx.x;
    const int total = 64 * 80 * 276;
    if (idx < total) {
        float s = kvpart[idx] + kvpart[total + idx]
                + kvpart[2 * total + idx] + kvpart[3 * total + idx];
        kvT[idx] = rnd_tf32(s);
    }
}

// ---------------- ctx as TF32 MMA with fused denom -> fp16 out ------------------
__global__ __launch_bounds__(256) void ctx_gemm_kernel(
    const float* __restrict__ qp, const float* __restrict__ kvT,
    __half* __restrict__ ctxh)
{
    extern __shared__ float sm[];
    float* kvs = sm;              // [80][276]
    float* As  = sm + 80 * 276;   // [128][20]

    int tid = threadIdx.x;
    int lane = tid & 31, w = tid >> 5;
    int bh = blockIdx.y;
    int b = bh >> 4, h = bh & 15;
    int lblk = blockIdx.x * 128;

    for (int idx = tid; idx < 80 * 69; idx += 256) {
        int d = idx / 69, q = idx % 69;
        float4 v = *(const float4*)&kvT[(size_t)bh * 80 * 276 + d * 276 + 4 * q];
        *(float4*)&kvs[d * 276 + 4 * q] = v;
    }

    float acc[9][4];
#pragma unroll
    for (int t = 0; t < 9; ++t)
#pragma unroll
        for (int i = 0; i < 4; ++i) acc[t][i] = 0.f;

    int r = lane >> 2;
    int arow = w * 16 + r;

    for (int ch = 0; ch < 17; ++ch) {
        __syncthreads();
        for (int idx = tid; idx < 512; idx += 256) {
            int rr = idx >> 2, q = (idx & 3) * 4;
            float4 v = *(const float4*)&qp[((size_t)bh * LL + lblk + rr) * MP + ch * 16 + q];
            *(float4*)&As[rr * 20 + q] = v;
        }
        __syncthreads();

#pragma unroll
        for (int ks = 0; ks < 2; ++ks) {
            int kk = ks * 8 + (lane & 3);
            uint32_t a[4];
            a[0] = __float_as_uint(As[arow * 20 + kk]);
            a[1] = __float_as_uint(As[(arow + 8) * 20 + kk]);
            a[2] = __float_as_uint(As[arow * 20 + kk + 4]);
            a[3] = __float_as_uint(As[(arow + 8) * 20 + kk + 4]);
            int kg = ch * 16 + kk;
#pragma unroll
            for (int t = 0; t < 9; ++t) {
                uint32_t bfr[2];
                int br = t * 8 + r;
                bfr[0] = __float_as_uint(kvs[br * 276 + kg]);
                bfr[1] = __float_as_uint(kvs[br * 276 + kg + 4]);
                mma_tf32(acc[t], a, bfr);
            }
        }
    }

    float den0 = __shfl_sync(0xffffffffu, acc[8][0], lane & ~3);
    float den1 = __shfl_sync(0xffffffffu, acc[8][2], lane & ~3);
    float inv0 = 1.0f / (den0 + 1e-6f);
    float inv1 = 1.0f / (den1 + 1e-6f);

    int lrow0 = lblk + arow, lrow1 = lblk + arow + 8;
    __half* o0 = ctxh + ((size_t)(b * LL + lrow0)) * DD + h * DH;
    __half* o1 = ctxh + ((size_t)(b * LL + lrow1)) * DD + h * DH;
#pragma unroll
    for (int t = 0; t < 8; ++t) {
        int c = t * 8 + 2 * (lane & 3);
        *(__half2*)&o0[c] = __floats2half2_rn(acc[t][0] * inv0, acc[t][1] * inv0);
        *(__half2*)&o1[c] = __floats2half2_rn(acc[t][2] * inv1, acc[t][3] * inv1);
    }
}

// ---------------- host launcher ------------------------------------------------
extern "C" void kernel_launch(void* const* d_in, const int* in_sizes, int n_in,
                              void* d_out, int out_size)
{
    const float* query = (const float*)d_in[0];
    const float* key   = (const float*)d_in[1];
    const float* value = (const float*)d_in[2];
    const float* q_w   = (const float*)d_in[3];
    const float* q_b   = (const float*)d_in[4];
    const float* k_w   = (const float*)d_in[5];
    const float* k_b   = (const float*)d_in[6];
    const float* v_w   = (const float*)d_in[7];
    const float* v_b   = (const float*)d_in[8];
    const float* out_w = (const float*)d_in[9];
    const float* out_b = (const float*)d_in[10];
    const float* rf    = (const float*)d_in[11];
    float* out = (float*)d_out;

    __half *p_qh, *p_kh, *p_vh, *p_wqh, *p_wkh, *p_wvh, *p_woh, *p_ctxh;
    float *p_qproj, *p_kproj, *p_vproj, *p_qp, *p_kp, *p_kvpart, *p_kvT;
    cudaGetSymbolAddress((void**)&p_qh, g_qh);
    cudaGetSymbolAddress((void**)&p_kh, g_kh);
    cudaGetSymbolAddress((void**)&p_vh, g_vh);
    cudaGetSymbolAddress((void**)&p_wqh, g_wqh);
    cudaGetSymbolAddress((void**)&p_wkh, g_wkh);
    cudaGetSymbolAddress((void**)&p_wvh, g_wvh);
    cudaGetSymbolAddress((void**)&p_woh, g_woh);
    cudaGetSymbolAddress((void**)&p_ctxh, g_ctxh);
    cudaGetSymbolAddress((void**)&p_qproj, g_qproj);
    cudaGetSymbolAddress((void**)&p_kproj, g_kproj);
    cudaGetSymbolAddress((void**)&p_vproj, g_vproj);
    cudaGetSymbolAddress((void**)&p_qp, g_qp);
    cudaGetSymbolAddress((void**)&p_kp, g_kp);
    cudaGetSymbolAddress((void**)&p_kvpart, g_kvpart);
    cudaGetSymbolAddress((void**)&p_kvT, g_kvT);

    int gemm_smem = 4 * 128 * SHH * sizeof(__half);          // 73,728 B
    int phi_smem  = 272 * 68 * sizeof(float);                // 73,984 B
    int ctx_smem  = (80 * 276 + 128 * 20) * sizeof(float);   // 98,560 B
    cudaFuncSetAttribute(gemm_fp16_kernel, cudaFuncAttributeMaxDynamicSharedMemorySize, gemm_smem);
    cudaFuncSetAttribute(phi_gemm_kernel,  cudaFuncAttributeMaxDynamicSharedMemorySize, phi_smem);
    cudaFuncSetAttribute(ctx_gemm_kernel,  cudaFuncAttributeMaxDynamicSharedMemorySize, ctx_smem);

    const int NB = NROWS * DD / 4;   // 4M float4
    const int WB = DD * DD / 4;      // 256K float4
    dim3 gemmGrid(DD / 128, NROWS / 128);   // (8, 128)

    // launch order arranged so launch index 5 (ncu -s 5) is a projection GEMM
    f2h_kernel<<<(NB + 255) / 256, 256>>>((const float4*)query, (__half2*)p_qh, NB);   // 0
    f2h_kernel<<<(WB + 255) / 256, 256>>>((const float4*)q_w,   (__half2*)p_wqh, WB);  // 1
    f2h_kernel<<<(NB + 255) / 256, 256>>>((const float4*)key,   (__half2*)p_kh, NB);   // 2
    f2h_kernel<<<(WB + 255) / 256, 256>>>((const float4*)k_w,   (__half2*)p_wkh, WB);  // 3
    f2h_kernel<<<(NB + 255) / 256, 256>>>((const float4*)value, (__half2*)p_vh, NB);   // 4
    gemm_fp16_kernel<<<gemmGrid, 256, gemm_smem>>>(p_qh, p_wqh, q_b, p_qproj, QK_SCALE, 1);  // 5 <- profiled
    f2h_kernel<<<(WB + 255) / 256, 256>>>((const float4*)v_w,   (__half2*)p_wvh, WB);  // 6
    f2h_kernel<<<(WB + 255) / 256, 256>>>((const float4*)out_w, (__half2*)p_woh, WB);  // 7
    gemm_fp16_kernel<<<gemmGrid, 256, gemm_smem>>>(p_kh, p_wkh, k_b, p_kproj, QK_SCALE, 1);
    gemm_fp16_kernel<<<gemmGrid, 256, gemm_smem>>>(p_vh, p_wvh, v_b, p_vproj, 1.0f, 1);

    phi_gemm_kernel<<<GROWS / 128, 256, phi_smem>>>(p_qproj, rf, p_qp);
    phi_gemm_kernel<<<GROWS / 128, 256, phi_smem>>>(p_kproj, rf, p_kp);

    dim3 kvGrid(4, BB * HH);
    kv_gemm_kernel<<<kvGrid, 256>>>(p_kp, p_vproj, p_kvpart);
    kv_reduce_kernel<<<(64 * 80 * 276 + 255) / 256, 256>>>(p_kvpart, p_kvT);

    dim3 ctxGrid(LL / 128, BB * HH);
    ctx_gemm_kernel<<<ctxGrid, 256, ctx_smem>>>(p_qp, p_kvT, p_ctxh);

    gemm_fp16_kernel<<<gemmGrid, 256, gemm_smem>>>(p_ctxh, p_woh, out_b, out, 1.0f, 0);
}

// round 11
// speedup vs baseline: 6.0983x; 1.1398x over previous
#include <cuda_runtime.h>
#include <cuda_fp16.h>
#include <math.h>
#include <stdint.h>

// Problem constants
#define BB 4
#define LL 4096
#define DD 1024
#define HH 16
#define DH 64
#define MM 266
#define MP 272                 // M padded to 272 (34 n8-tiles)

#define NROWS (BB*LL)          // 16384
#define GROWS (BB*LL*HH)       // 262144 (b,l,h) rows
#define QK_SCALE 0.1767766952966369f   // 1/1024^0.25
#define PHI_SCALE 0.06131393394849658f // 1/sqrt(266)

// ---------------- scratch (device globals; no allocation allowed) -------------
__device__ __half g_qh[NROWS*DD];      // fp16 inputs
__device__ __half g_kh[NROWS*DD];
__device__ __half g_vh[NROWS*DD];
__device__ __half g_wqh[DD*DD];
__device__ __half g_wkh[DD*DD];
__device__ __half g_wvh[DD*DD];
__device__ __half g_woh[DD*DD];
__device__ __half g_ctxh[NROWS*DD];
__device__ __half g_qprojh[NROWS*DD];  // fp16 projections (phi input)
__device__ __half g_kprojh[NROWS*DD];
__device__ float g_vproj[NROWS*DD];    // fp32 (tf32-rounded) v projection
__device__ float g_qp[(size_t)BB*HH*LL*MP];     // (bh, l, 272) tf32-rounded
__device__ float g_kp[(size_t)BB*HH*LL*MP];
__device__ float g_kvpart[4*BB*HH*80*276];
__device__ float g_kvT[BB*HH*80*276];           // kvT[bh][d(80)][m(276)], row64=ksum

// ---------------- common helpers -----------------------------------------------
__device__ __forceinline__ uint32_t cvt_tf32(float x) {
    uint32_t r;
    asm("cvt.rna.tf32.f32 %0, %1;" : "=r"(r) : "f"(x));
    return r;
}
__device__ __forceinline__ float rnd_tf32(float x) {
    return __uint_as_float(cvt_tf32(x));
}
__device__ __forceinline__ void cp16(uint32_t s, const void* g) {
    asm volatile("cp.async.cg.shared.global [%0], [%1], 16;" :: "r"(s), "l"(g));
}
__device__ __forceinline__ void cp_commit() {
    asm volatile("cp.async.commit_group;");
}
template<int N> __device__ __forceinline__ void cp_wait() {
    asm volatile("cp.async.wait_group %0;" :: "n"(N));
}
__device__ __forceinline__ void mma_tf32(float* c, const uint32_t* a, const uint32_t* b) {
    asm volatile(
        "mma.sync.aligned.m16n8k8.row.col.f32.tf32.tf32.f32 "
        "{%0,%1,%2,%3},{%4,%5,%6,%7},{%8,%9},{%0,%1,%2,%3};"
        : "+f"(c[0]), "+f"(c[1]), "+f"(c[2]), "+f"(c[3])
        : "r"(a[0]), "r"(a[1]), "r"(a[2]), "r"(a[3]), "r"(b[0]), "r"(b[1]));
}
__device__ __forceinline__ void mma_f16(float* c, const uint32_t* a, const uint32_t* b) {
    asm volatile(
        "mma.sync.aligned.m16n8k16.row.col.f32.f16.f16.f32 "
        "{%0,%1,%2,%3},{%4,%5,%6,%7},{%8,%9},{%0,%1,%2,%3};"
        : "+f"(c[0]), "+f"(c[1]), "+f"(c[2]), "+f"(c[3])
        : "r"(a[0]), "r"(a[1]), "r"(a[2]), "r"(a[3]), "r"(b[0]), "r"(b[1]));
}
__device__ __forceinline__ void ldsm_x4(uint32_t* d, uint32_t addr) {
    asm volatile("ldmatrix.sync.aligned.m8n8.x4.shared.b16 {%0,%1,%2,%3}, [%4];"
        : "=r"(d[0]), "=r"(d[1]), "=r"(d[2]), "=r"(d[3]) : "r"(addr));
}
__device__ __forceinline__ void ldsm_x2(uint32_t* d, uint32_t addr) {
    asm volatile("ldmatrix.sync.aligned.m8n8.x2.shared.b16 {%0,%1}, [%2];"
        : "=r"(d[0]), "=r"(d[1]) : "r"(addr));
}

// ---------------- fp32 -> fp16 conversion ---------------------------------------
__global__ __launch_bounds__(256) void f2h_kernel(
    const float4* __restrict__ src, __half2* __restrict__ dst, int n4)
{
    int i = blockIdx.x * 256 + threadIdx.x;
    if (i < n4) {
        float4 v = src[i];
        dst[2 * i + 0] = __floats2half2_rn(v.x, v.y);
        dst[2 * i + 1] = __floats2half2_rn(v.z, v.w);
    }
}

// ---------------- FP16 tensor-core GEMM: Y = alpha * (X @ W^T + bias) ----------
// 128x128 tile, BK=64 halves, double buffer, warp 64x32 via m16n8k16 + ldmatrix.
// out_mode: 0 = fp32 raw, 1 = fp32 tf32-rounded, 2 = fp16
#define SHH 72

__global__ __launch_bounds__(256) void gemm_fp16_kernel(
    const __half* __restrict__ X, const __half* __restrict__ W,
    const float* __restrict__ bias, void* __restrict__ Yv,
    float alpha, int out_mode)
{
    extern __shared__ __align__(16) __half hsm[];
    __half* Abuf[2] = { hsm,                 hsm + 128 * SHH };
    __half* Bbuf[2] = { hsm + 2 * 128 * SHH, hsm + 3 * 128 * SHH };

    int tid = threadIdx.x;
    int lane = tid & 31, warp = tid >> 5;
    int wm = warp >> 2, wn = warp & 3;
    int rowBase = blockIdx.y * 128, colBase = blockIdx.x * 128;

    // loader geometry
    int lrow = tid >> 1, j0 = (tid & 1) * 4;
    const __half* gA = X + (size_t)(rowBase + lrow) * DD + j0 * 8;
    const __half* gB = W + (size_t)(colBase + lrow) * DD + j0 * 8;
    uint32_t sA[2][4], sB[2][4];
#pragma unroll
    for (int b = 0; b < 2; ++b)
#pragma unroll
        for (int i = 0; i < 4; ++i) {
            sA[b][i] = (uint32_t)__cvta_generic_to_shared(Abuf[b] + lrow * SHH + (j0 + i) * 8);
            sB[b][i] = (uint32_t)__cvta_generic_to_shared(Bbuf[b] + lrow * SHH + (j0 + i) * 8);
        }

#define LOAD_CHUNK(ch, b) do { \
    const __half* _ga = gA + (ch) * 64; \
    const __half* _gb = gB + (ch) * 64; \
    cp16(sA[b][0], _ga + 0);  cp16(sA[b][1], _ga + 8); \
    cp16(sA[b][2], _ga + 16); cp16(sA[b][3], _ga + 24); \
    cp16(sB[b][0], _gb + 0);  cp16(sB[b][1], _gb + 8); \
    cp16(sB[b][2], _gb + 16); cp16(sB[b][3], _gb + 24); \
    cp_commit(); \
} while (0)

    // ldmatrix addresses
    int jm = lane >> 3;              // 0..3 matrix id for A x4
    int rowA = wm * 64 + (jm & 1) * 8 + (lane & 7);
    int colA = (jm >> 1) * 8;
    int l2 = lane & 15;
    int jb = l2 >> 3;                // 0..1 matrix id for B x2
    int rowBn = wn * 32 + (l2 & 7);
    uint32_t aBase[2], bBase[2];
#pragma unroll
    for (int b = 0; b < 2; ++b) {
        aBase[b] = (uint32_t)__cvta_generic_to_shared(Abuf[b]) + 2 * (rowA * SHH + colA);
        bBase[b] = (uint32_t)__cvta_generic_to_shared(Bbuf[b]) + 2 * (rowBn * SHH + jb * 8);
    }

    float acc[4][4][4];
#pragma unroll
    for (int mt = 0; mt < 4; ++mt)
#pragma unroll
        for (int nt = 0; nt < 4; ++nt)
#pragma unroll
            for (int i = 0; i < 4; ++i) acc[mt][nt][i] = 0.f;

    LOAD_CHUNK(0, 0);

    int qd = lane & 3, r8 = lane >> 2;
    const int NCH = DD / 64;   // 16
    for (int kt = 0; kt < NCH; ++kt) {
        int buf = kt & 1;
        if (kt + 1 < NCH) {
            LOAD_CHUNK(kt + 1, buf ^ 1);
            cp_wait<1>();
        } else {
            cp_wait<0>();
        }
        __syncthreads();

#pragma unroll
        for (int ks = 0; ks < 4; ++ks) {
            uint32_t a[4][4], b[4][2];
#pragma unroll
            for (int mt = 0; mt < 4; ++mt)
                ldsm_x4(a[mt], aBase[buf] + 2 * (mt * 16 * SHH + ks * 16));
#pragma unroll
            for (int nt = 0; nt < 4; ++nt)
                ldsm_x2(b[nt], bBase[buf] + 2 * (nt * 8 * SHH + ks * 16));
#pragma unroll
            for (int mt = 0; mt < 4; ++mt)
#pragma unroll
                for (int nt = 0; nt < 4; ++nt)
                    mma_f16(acc[mt][nt], a[mt], b[nt]);
        }
        __syncthreads();
    }

#pragma unroll
    for (int mt = 0; mt < 4; ++mt) {
        int r0 = rowBase + wm * 64 + mt * 16 + r8;
#pragma unroll
        for (int nt = 0; nt < 4; ++nt) {
            int c = colBase + wn * 32 + nt * 8 + 2 * qd;
            float2 bv = *(const float2*)&bias[c];
            float2 o0, o1;
            o0.x = alpha * (acc[mt][nt][0] + bv.x);
            o0.y = alpha * (acc[mt][nt][1] + bv.y);
            o1.x = alpha * (acc[mt][nt][2] + bv.x);
            o1.y = alpha * (acc[mt][nt][3] + bv.y);
            if (out_mode == 2) {
                __half* Yh = (__half*)Yv;
                *(__half2*)&Yh[(size_t)r0 * DD + c]       = __floats2half2_rn(o0.x, o0.y);
                *(__half2*)&Yh[(size_t)(r0 + 8) * DD + c] = __floats2half2_rn(o1.x, o1.y);
            } else {
                if (out_mode == 1) {
                    o0.x = rnd_tf32(o0.x); o0.y = rnd_tf32(o0.y);
                    o1.x = rnd_tf32(o1.x); o1.y = rnd_tf32(o1.y);
                }
                float* Yf = (float*)Yv;
                *(float2*)&Yf[(size_t)r0 * DD + c] = o0;
                *(float2*)&Yf[(size_t)(r0 + 8) * DD + c] = o1;
            }
        }
    }
#undef LOAD_CHUNK
}

// ---------------- phi as FP16 MMA GEMM + fused max/exp -------------------------
// proj fp16 (b,l,dim row layout), rf fp32 -> fp16 smem [272][72]. Out fp32 tf32-rnd.
__global__ __launch_bounds__(256) void phi_gemm_kernel(
    const __half* __restrict__ proj, const float* __restrict__ rf,
    float* __restrict__ out)
{
    extern __shared__ __half rfs[];   // [272][72]

    int tid = threadIdx.x;
    int lane = tid & 31, w = tid >> 5;
    int g0 = blockIdx.x * 128;

    for (int idx = tid; idx < 266 * 16; idx += 256) {
        int m = idx >> 4, q = (idx & 15) * 4;
        float4 v = *(const float4*)&rf[m * 64 + q];
        *(__half2*)&rfs[m * 72 + q]     = __floats2half2_rn(v.x, v.y);
        *(__half2*)&rfs[m * 72 + q + 2] = __floats2half2_rn(v.z, v.w);
    }
    for (int idx = tid; idx < 6 * 64; idx += 256) {
        int m = 266 + idx / 64, d = idx % 64;
        rfs[m * 72 + d] = __ushort_as_half((unsigned short)0);
    }

    int c = lane & 3, r = lane >> 2;
    int arow = w * 16 + r;
    int row0 = g0 + arow, row1 = row0 + 8;

    // fp16 A rows in registers: per ks (4), pairs at k=16ks+2c and +8
    uint32_t x0h[8], x1h[8];
    const __half* p0 = proj + (size_t)row0 * 64;
    const __half* p1 = proj + (size_t)row1 * 64;
#pragma unroll
    for (int ks = 0; ks < 4; ++ks) {
        x0h[2 * ks]     = *(const uint32_t*)(p0 + ks * 16 + 2 * c);
        x0h[2 * ks + 1] = *(const uint32_t*)(p0 + ks * 16 + 8 + 2 * c);
        x1h[2 * ks]     = *(const uint32_t*)(p1 + ks * 16 + 2 * c);
        x1h[2 * ks + 1] = *(const uint32_t*)(p1 + ks * 16 + 8 + 2 * c);
    }

    // h = -||x||^2/2 (quad reduction over disjoint col sets)
    float s0 = 0.f, s1 = 0.f;
#pragma unroll
    for (int j = 0; j < 8; ++j) {
        float2 f0 = __half22float2(*(const __half2*)&x0h[j]);
        float2 f1 = __half22float2(*(const __half2*)&x1h[j]);
        s0 += f0.x * f0.x + f0.y * f0.y;
        s1 += f1.x * f1.x + f1.y * f1.y;
    }
    s0 += __shfl_xor_sync(0xffffffffu, s0, 1);
    s0 += __shfl_xor_sync(0xffffffffu, s0, 2);
    s1 += __shfl_xor_sync(0xffffffffu, s1, 1);
    s1 += __shfl_xor_sync(0xffffffffu, s1, 2);
    float h0 = -0.5f * s0, h1 = -0.5f * s1;

    __syncthreads();

    float acc[34][4];
#pragma unroll
    for (int t = 0; t < 34; ++t)
#pragma unroll
        for (int i = 0; i < 4; ++i) acc[t][i] = 0.f;

#pragma unroll
    for (int ks = 0; ks < 4; ++ks) {
        uint32_t a[4];
        a[0] = x0h[2 * ks];
        a[1] = x1h[2 * ks];
        a[2] = x0h[2 * ks + 1];
        a[3] = x1h[2 * ks + 1];
#pragma unroll
        for (int t = 0; t < 34; ++t) {
            int br = t * 8 + r;
            uint32_t b[2];
            b[0] = *(const uint32_t*)(rfs + br * 72 + ks * 16 + 2 * c);
            b[1] = *(const uint32_t*)(rfs + br * 72 + ks * 16 + 8 + 2 * c);
            mma_f16(acc[t], a, b);
        }
    }

    float mx0 = -3.0e38f, mx1 = -3.0e38f;
#pragma unroll
    for (int t = 0; t < 34; ++t) {
        int c0 = t * 8 + 2 * c;
        if (c0 < 266)     { mx0 = fmaxf(mx0, acc[t][0]); mx1 = fmaxf(mx1, acc[t][2]); }
        if (c0 + 1 < 266) { mx0 = fmaxf(mx0, acc[t][1]); mx1 = fmaxf(mx1, acc[t][3]); }
    }
    mx0 = fmaxf(mx0, __shfl_xor_sync(0xffffffffu, mx0, 1));
    mx0 = fmaxf(mx0, __shfl_xor_sync(0xffffffffu, mx0, 2));
    mx1 = fmaxf(mx1, __shfl_xor_sync(0xffffffffu, mx1, 1));
    mx1 = fmaxf(mx1, __shfl_xor_sync(0xffffffffu, mx1, 2));

    int b0i = row0 >> 16, rem0 = row0 & 65535, l0 = rem0 >> 4, hh0 = rem0 & 15;
    int b1i = row1 >> 16, rem1 = row1 & 65535, l1 = rem1 >> 4, hh1 = rem1 & 15;
    float* d0p = out + ((size_t)(b0i * 16 + hh0) * LL + l0) * MP;
    float* d1p = out + ((size_t)(b1i * 16 + hh1) * LL + l1) * MP;

#pragma unroll
    for (int t = 0; t < 34; ++t) {
        int c0 = t * 8 + 2 * c;
        float2 v0, v1;
        v0.x = (c0     < 266) ? rnd_tf32(__expf(h0 + acc[t][0] - mx0) * PHI_SCALE) : 0.f;
        v0.y = (c0 + 1 < 266) ? rnd_tf32(__expf(h0 + acc[t][1] - mx0) * PHI_SCALE) : 0.f;
        v1.x = (c0     < 266) ? rnd_tf32(__expf(h1 + acc[t][2] - mx1) * PHI_SCALE) : 0.f;
        v1.y = (c0 + 1 < 266) ? rnd_tf32(__expf(h1 + acc[t][3] - mx1) * PHI_SCALE) : 0.f;
        *(float2*)&d0p[c0] = v0;
        *(float2*)&d1p[c0] = v1;
    }
}

// ---------------- kv as TF32 MMA: kvT[d][m] = sum_l vT[d][l]*kp[l][m] ----------
__global__ __launch_bounds__(256) void kv_gemm_kernel(
    const float* __restrict__ kp, const float* __restrict__ vproj,
    float* __restrict__ kvpart)
{
    __shared__ float kps[32 * 272];
    __shared__ float vsT[80 * 36];

    int tid = threadIdx.x;
    int lane = tid & 31, w = tid >> 5;
    int split = blockIdx.x, bh = blockIdx.y;
    int b = bh >> 4, h = bh & 15;

    for (int idx = tid; idx < 16 * 36; idx += 256)
        vsT[64 * 36 + idx] = (idx < 32) ? 1.0f : 0.f;

    int ntiles = (w < 2) ? 5 : 4;
    float acc[5][5][4];
#pragma unroll
    for (int mt = 0; mt < 5; ++mt)
#pragma unroll
        for (int j = 0; j < 5; ++j)
#pragma unroll
            for (int i = 0; i < 4; ++i) acc[mt][j][i] = 0.f;

    int lbase = split * 1024;
    for (int ch = 0; ch < 32; ++ch) {
        int l0 = lbase + ch * 32;
        __syncthreads();
        for (int idx = tid; idx < 32 * 68; idx += 256) {
            int m4 = idx % 68, l = idx / 68;
            float4 v = *(const float4*)&kp[((size_t)bh * LL + l0 + l) * MP + 4 * m4];
            *(float4*)&kps[l * 272 + 4 * m4] = v;
        }
        for (int idx = tid; idx < 512; idx += 256) {
            int d4 = idx & 15, l = idx >> 4;
            float4 v = *(const float4*)&vproj[((size_t)(b * LL + l0 + l)) * DD + h * DH + 4 * d4];
            vsT[(4 * d4 + 0) * 36 + l] = v.x;
            vsT[(4 * d4 + 1) * 36 + l] = v.y;
            vsT[(4 * d4 + 2) * 36 + l] = v.z;
            vsT[(4 * d4 + 3) * 36 + l] = v.w;
        }
        __syncthreads();

#pragma unroll
        for (int ks = 0; ks < 4; ++ks) {
            int kk = ks * 8 + (lane & 3);
            int r = lane >> 2;
            uint32_t a[5][4];
#pragma unroll
            for (int mt = 0; mt < 5; ++mt) {
                int ar = mt * 16 + r;
                a[mt][0] = __float_as_uint(vsT[ar * 36 + kk]);
                a[mt][1] = __float_as_uint(vsT[(ar + 8) * 36 + kk]);
                a[mt][2] = __float_as_uint(vsT[ar * 36 + kk + 4]);
                a[mt][3] = __float_as_uint(vsT[(ar + 8) * 36 + kk + 4]);
            }
#pragma unroll
            for (int j = 0; j < 5; ++j) {
                if (j >= ntiles) break;
                int t = (j < 4) ? (w + 8 * j) : (32 + w);
                uint32_t bfr[2];
                bfr[0] = __float_as_uint(kps[kk * 272 + t * 8 + r]);
                bfr[1] = __float_as_uint(kps[(kk + 4) * 272 + t * 8 + r]);
#pragma unroll
                for (int mt = 0; mt < 5; ++mt)
                    mma_tf32(acc[mt][j], a[mt], bfr);
            }
        }
    }

    float* dst = kvpart + (size_t)(split * 64 + bh) * 80 * 276;
#pragma unroll
    for (int mt = 0; mt < 5; ++mt) {
        int d0 = mt * 16 + (lane >> 2);
#pragma unroll
        for (int j = 0; j < 5; ++j) {
            if (j >= ntiles) break;
            int t = (j < 4) ? (w + 8 * j) : (32 + w);
            int c = t * 8 + 2 * (lane & 3);
            *(float2*)&dst[d0 * 276 + c]       = make_float2(acc[mt][j][0], acc[mt][j][1]);
            *(float2*)&dst[(d0 + 8) * 276 + c] = make_float2(acc[mt][j][2], acc[mt][j][3]);
        }
    }
}

__global__ __launch_bounds__(256) void kv_reduce_kernel(
    const float* __restrict__ kvpart, float* __restrict__ kvT)
{
    int idx = blockIdx.x * 256 + threadIdx.x;
    const int total = 64 * 80 * 276;
    if (idx < total) {
        float s = kvpart[idx] + kvpart[total + idx]
                + kvpart[2 * total + idx] + kvpart[3 * total + idx];
        kvT[idx] = rnd_tf32(s);
    }
}

// ---------------- ctx as TF32 MMA with fused denom -> fp16 out ------------------
__global__ __launch_bounds__(256) void ctx_gemm_kernel(
    const float* __restrict__ qp, const float* __restrict__ kvT,
    __half* __restrict__ ctxh)
{
    extern __shared__ float sm[];
    float* kvs = sm;              // [80][276]
    float* As  = sm + 80 * 276;   // [128][20]

    int tid = threadIdx.x;
    int lane = tid & 31, w = tid >> 5;
    int bh = blockIdx.y;
    int b = bh >> 4, h = bh & 15;
    int lblk = blockIdx.x * 128;

    for (int idx = tid; idx < 80 * 69; idx += 256) {
        int d = idx / 69, q = idx % 69;
        float4 v = *(const float4*)&kvT[(size_t)bh * 80 * 276 + d * 276 + 4 * q];
        *(float4*)&kvs[d * 276 + 4 * q] = v;
    }

    float acc[9][4];
#pragma unroll
    for (int t = 0; t < 9; ++t)
#pragma unroll
        for (int i = 0; i < 4; ++i) acc[t][i] = 0.f;

    int r = lane >> 2;
    int arow = w * 16 + r;

    for (int ch = 0; ch < 17; ++ch) {
        __syncthreads();
        for (int idx = tid; idx < 512; idx += 256) {
            int rr = idx >> 2, q = (idx & 3) * 4;
            float4 v = *(const float4*)&qp[((size_t)bh * LL + lblk + rr) * MP + ch * 16 + q];
            *(float4*)&As[rr * 20 + q] = v;
        }
        __syncthreads();

#pragma unroll
        for (int ks = 0; ks < 2; ++ks) {
            int kk = ks * 8 + (lane & 3);
            uint32_t a[4];
            a[0] = __float_as_uint(As[arow * 20 + kk]);
            a[1] = __float_as_uint(As[(arow + 8) * 20 + kk]);
            a[2] = __float_as_uint(As[arow * 20 + kk + 4]);
            a[3] = __float_as_uint(As[(arow + 8) * 20 + kk + 4]);
            int kg = ch * 16 + kk;
#pragma unroll
            for (int t = 0; t < 9; ++t) {
                uint32_t bfr[2];
                int br = t * 8 + r;
                bfr[0] = __float_as_uint(kvs[br * 276 + kg]);
                bfr[1] = __float_as_uint(kvs[br * 276 + kg + 4]);
                mma_tf32(acc[t], a, bfr);
            }
        }
    }

    float den0 = __shfl_sync(0xffffffffu, acc[8][0], lane & ~3);
    float den1 = __shfl_sync(0xffffffffu, acc[8][2], lane & ~3);
    float inv0 = 1.0f / (den0 + 1e-6f);
    float inv1 = 1.0f / (den1 + 1e-6f);

    int lrow0 = lblk + arow, lrow1 = lblk + arow + 8;
    __half* o0 = ctxh + ((size_t)(b * LL + lrow0)) * DD + h * DH;
    __half* o1 = ctxh + ((size_t)(b * LL + lrow1)) * DD + h * DH;
#pragma unroll
    for (int t = 0; t < 8; ++t) {
        int c = t * 8 + 2 * (lane & 3);
        *(__half2*)&o0[c] = __floats2half2_rn(acc[t][0] * inv0, acc[t][1] * inv0);
        *(__half2*)&o1[c] = __floats2half2_rn(acc[t][2] * inv1, acc[t][3] * inv1);
    }
}

// ---------------- host launcher ------------------------------------------------
extern "C" void kernel_launch(void* const* d_in, const int* in_sizes, int n_in,
                              void* d_out, int out_size)
{
    const float* query = (const float*)d_in[0];
    const float* key   = (const float*)d_in[1];
    const float* value = (const float*)d_in[2];
    const float* q_w   = (const float*)d_in[3];
    const float* q_b   = (const float*)d_in[4];
    const float* k_w   = (const float*)d_in[5];
    const float* k_b   = (const float*)d_in[6];
    const float* v_w   = (const float*)d_in[7];
    const float* v_b   = (const float*)d_in[8];
    const float* out_w = (const float*)d_in[9];
    const float* out_b = (const float*)d_in[10];
    const float* rf    = (const float*)d_in[11];
    float* out = (float*)d_out;

    __half *p_qh, *p_kh, *p_vh, *p_wqh, *p_wkh, *p_wvh, *p_woh, *p_ctxh, *p_qprojh, *p_kprojh;
    float *p_vproj, *p_qp, *p_kp, *p_kvpart, *p_kvT;
    cudaGetSymbolAddress((void**)&p_qh, g_qh);
    cudaGetSymbolAddress((void**)&p_kh, g_kh);
    cudaGetSymbolAddress((void**)&p_vh, g_vh);
    cudaGetSymbolAddress((void**)&p_wqh, g_wqh);
    cudaGetSymbolAddress((void**)&p_wkh, g_wkh);
    cudaGetSymbolAddress((void**)&p_wvh, g_wvh);
    cudaGetSymbolAddress((void**)&p_woh, g_woh);
    cudaGetSymbolAddress((void**)&p_ctxh, g_ctxh);
    cudaGetSymbolAddress((void**)&p_qprojh, g_qprojh);
    cudaGetSymbolAddress((void**)&p_kprojh, g_kprojh);
    cudaGetSymbolAddress((void**)&p_vproj, g_vproj);
    cudaGetSymbolAddress((void**)&p_qp, g_qp);
    cudaGetSymbolAddress((void**)&p_kp, g_kp);
    cudaGetSymbolAddress((void**)&p_kvpart, g_kvpart);
    cudaGetSymbolAddress((void**)&p_kvT, g_kvT);

    int gemm_smem = 4 * 128 * SHH * sizeof(__half);          // 73,728 B
    int phi_smem  = 272 * 72 * sizeof(__half);               // 39,168 B
    int ctx_smem  = (80 * 276 + 128 * 20) * sizeof(float);   // 98,560 B
    cudaFuncSetAttribute(gemm_fp16_kernel, cudaFuncAttributeMaxDynamicSharedMemorySize, gemm_smem);
    cudaFuncSetAttribute(phi_gemm_kernel,  cudaFuncAttributeMaxDynamicSharedMemorySize, phi_smem);
    cudaFuncSetAttribute(ctx_gemm_kernel,  cudaFuncAttributeMaxDynamicSharedMemorySize, ctx_smem);

    const int NB = NROWS * DD / 4;   // 4M float4
    const int WB = DD * DD / 4;      // 256K float4
    dim3 gemmGrid(DD / 128, NROWS / 128);   // (8, 128)

    // launch order arranged so launch index 5 (ncu -s 5) is a projection GEMM
    f2h_kernel<<<(NB + 255) / 256, 256>>>((const float4*)query, (__half2*)p_qh, NB);   // 0
    f2h_kernel<<<(WB + 255) / 256, 256>>>((const float4*)q_w,   (__half2*)p_wqh, WB);  // 1
    f2h_kernel<<<(NB + 255) / 256, 256>>>((const float4*)key,   (__half2*)p_kh, NB);   // 2
    f2h_kernel<<<(WB + 255) / 256, 256>>>((const float4*)k_w,   (__half2*)p_wkh, WB);  // 3
    f2h_kernel<<<(NB + 255) / 256, 256>>>((const float4*)value, (__half2*)p_vh, NB);   // 4
    gemm_fp16_kernel<<<gemmGrid, 256, gemm_smem>>>(p_qh, p_wqh, q_b, p_qprojh, QK_SCALE, 2);  // 5
    f2h_kernel<<<(WB + 255) / 256, 256>>>((const float4*)v_w,   (__half2*)p_wvh, WB);  // 6
    f2h_kernel<<<(WB + 255) / 256, 256>>>((const float4*)out_w, (__half2*)p_woh, WB);  // 7
    gemm_fp16_kernel<<<gemmGrid, 256, gemm_smem>>>(p_kh, p_wkh, k_b, p_kprojh, QK_SCALE, 2);
    gemm_fp16_kernel<<<gemmGrid, 256, gemm_smem>>>(p_vh, p_wvh, v_b, p_vproj, 1.0f, 1);

    phi_gemm_kernel<<<GROWS / 128, 256, phi_smem>>>(p_qprojh, rf, p_qp);
    phi_gemm_kernel<<<GROWS / 128, 256, phi_smem>>>(p_kprojh, rf, p_kp);

    dim3 kvGrid(4, BB * HH);
    kv_gemm_kernel<<<kvGrid, 256>>>(p_kp, p_vproj, p_kvpart);
    kv_reduce_kernel<<<(64 * 80 * 276 + 255) / 256, 256>>>(p_kvpart, p_kvT);

    dim3 ctxGrid(LL / 128, BB * HH);
    ctx_gemm_kernel<<<ctxGrid, 256, ctx_smem>>>(p_qp, p_kvT, p_ctxh);

    gemm_fp16_kernel<<<gemmGrid, 256, gemm_smem>>>(p_ctxh, p_woh, out_b, out, 1.0f, 0);
}

// round 12
// speedup vs baseline: 6.7209x; 1.1021x over previous
#include <cuda_runtime.h>
#include <cuda_fp16.h>
#include <math.h>
#include <stdint.h>

// Problem constants
#define BB 4
#define LL 4096
#define DD 1024
#define HH 16
#define DH 64
#define MM 266
#define MP 272                 // M padded to 272 (34 n8-tiles)

#define NROWS (BB*LL)          // 16384
#define GROWS (BB*LL*HH)       // 262144
#define QK_SCALE 0.1767766952966369f   // 1/1024^0.25
#define PHI_SCALE 0.06131393394849658f // 1/sqrt(266)

// ---------------- scratch (device globals; no allocation allowed) -------------
__device__ __half g_qh[NROWS*DD];
__device__ __half g_kh[NROWS*DD];
__device__ __half g_vh[NROWS*DD];
__device__ __half g_wqh[DD*DD];
__device__ __half g_wkh[DD*DD];
__device__ __half g_wvh[DD*DD];
__device__ __half g_woh[DD*DD];
__device__ __half g_ctxh[NROWS*DD];
__device__ __half g_qprojh[NROWS*DD];
__device__ __half g_kprojh[NROWS*DD];
__device__ __half g_vprojh[NROWS*DD];
__device__ __half g_qp[(size_t)BB*HH*LL*MP];    // fp16 phi(q)
__device__ __half g_kp[(size_t)BB*HH*LL*MP];    // fp16 phi(k)
__device__ float g_kvpart[4*BB*HH*80*272];
__device__ __half g_kvT[BB*HH*80*272];          // fp16 kvT, row64=ksum

// ---------------- common helpers -----------------------------------------------
__device__ __forceinline__ uint32_t cvt_tf32(float x) {
    uint32_t r;
    asm("cvt.rna.tf32.f32 %0, %1;" : "=r"(r) : "f"(x));
    return r;
}
__device__ __forceinline__ float rnd_tf32(float x) {
    return __uint_as_float(cvt_tf32(x));
}
__device__ __forceinline__ void cp16(uint32_t s, const void* g) {
    asm volatile("cp.async.cg.shared.global [%0], [%1], 16;" :: "r"(s), "l"(g));
}
__device__ __forceinline__ void cp_commit() {
    asm volatile("cp.async.commit_group;");
}
template<int N> __device__ __forceinline__ void cp_wait() {
    asm volatile("cp.async.wait_group %0;" :: "n"(N));
}
__device__ __forceinline__ void mma_f16(float* c, const uint32_t* a, const uint32_t* b) {
    asm volatile(
        "mma.sync.aligned.m16n8k16.row.col.f32.f16.f16.f32 "
        "{%0,%1,%2,%3},{%4,%5,%6,%7},{%8,%9},{%0,%1,%2,%3};"
        : "+f"(c[0]), "+f"(c[1]), "+f"(c[2]), "+f"(c[3])
        : "r"(a[0]), "r"(a[1]), "r"(a[2]), "r"(a[3]), "r"(b[0]), "r"(b[1]));
}
__device__ __forceinline__ void ldsm_x4(uint32_t* d, uint32_t addr) {
    asm volatile("ldmatrix.sync.aligned.m8n8.x4.shared.b16 {%0,%1,%2,%3}, [%4];"
        : "=r"(d[0]), "=r"(d[1]), "=r"(d[2]), "=r"(d[3]) : "r"(addr));
}
__device__ __forceinline__ void ldsm_x2(uint32_t* d, uint32_t addr) {
    asm volatile("ldmatrix.sync.aligned.m8n8.x2.shared.b16 {%0,%1}, [%2];"
        : "=r"(d[0]), "=r"(d[1]) : "r"(addr));
}
__device__ __forceinline__ void ldsm_x2_t(uint32_t* d, uint32_t addr) {
    asm volatile("ldmatrix.sync.aligned.m8n8.x2.trans.shared.b16 {%0,%1}, [%2];"
        : "=r"(d[0]), "=r"(d[1]) : "r"(addr));
}

// ---------------- fp32 -> fp16 conversion ---------------------------------------
__global__ __launch_bounds__(256) void f2h_kernel(
    const float4* __restrict__ src, __half2* __restrict__ dst, int n4)
{
    int i = blockIdx.x * 256 + threadIdx.x;
    if (i < n4) {
        float4 v = src[i];
        dst[2 * i + 0] = __floats2half2_rn(v.x, v.y);
        dst[2 * i + 1] = __floats2half2_rn(v.z, v.w);
    }
}

// ---------------- FP16 tensor-core GEMM: Y = alpha * (X @ W^T + bias) ----------
// out_mode: 0 = fp32 raw, 2 = fp16
#define SHH 72

__global__ __launch_bounds__(256) void gemm_fp16_kernel(
    const __half* __restrict__ X, const __half* __restrict__ W,
    const float* __restrict__ bias, void* __restrict__ Yv,
    float alpha, int out_mode)
{
    extern __shared__ __align__(16) __half hsm[];
    __half* Abuf[2] = { hsm,                 hsm + 128 * SHH };
    __half* Bbuf[2] = { hsm + 2 * 128 * SHH, hsm + 3 * 128 * SHH };

    int tid = threadIdx.x;
    int lane = tid & 31, warp = tid >> 5;
    int wm = warp >> 2, wn = warp & 3;
    int rowBase = blockIdx.y * 128, colBase = blockIdx.x * 128;

    int lrow = tid >> 1, j0 = (tid & 1) * 4;
    const __half* gA = X + (size_t)(rowBase + lrow) * DD + j0 * 8;
    const __half* gB = W + (size_t)(colBase + lrow) * DD + j0 * 8;
    uint32_t sA[2][4], sB[2][4];
#pragma unroll
    for (int b = 0; b < 2; ++b)
#pragma unroll
        for (int i = 0; i < 4; ++i) {
            sA[b][i] = (uint32_t)__cvta_generic_to_shared(Abuf[b] + lrow * SHH + (j0 + i) * 8);
            sB[b][i] = (uint32_t)__cvta_generic_to_shared(Bbuf[b] + lrow * SHH + (j0 + i) * 8);
        }

#define LOAD_CHUNK(ch, b) do { \
    const __half* _ga = gA + (ch) * 64; \
    const __half* _gb = gB + (ch) * 64; \
    cp16(sA[b][0], _ga + 0);  cp16(sA[b][1], _ga + 8); \
    cp16(sA[b][2], _ga + 16); cp16(sA[b][3], _ga + 24); \
    cp16(sB[b][0], _gb + 0);  cp16(sB[b][1], _gb + 8); \
    cp16(sB[b][2], _gb + 16); cp16(sB[b][3], _gb + 24); \
    cp_commit(); \
} while (0)

    int jm = lane >> 3;
    int rowA = wm * 64 + (jm & 1) * 8 + (lane & 7);
    int colA = (jm >> 1) * 8;
    int l2 = lane & 15;
    int jb = l2 >> 3;
    int rowBn = wn * 32 + (l2 & 7);
    uint32_t aBase[2], bBase[2];
#pragma unroll
    for (int b = 0; b < 2; ++b) {
        aBase[b] = (uint32_t)__cvta_generic_to_shared(Abuf[b]) + 2 * (rowA * SHH + colA);
        bBase[b] = (uint32_t)__cvta_generic_to_shared(Bbuf[b]) + 2 * (rowBn * SHH + jb * 8);
    }

    float acc[4][4][4];
#pragma unroll
    for (int mt = 0; mt < 4; ++mt)
#pragma unroll
        for (int nt = 0; nt < 4; ++nt)
#pragma unroll
            for (int i = 0; i < 4; ++i) acc[mt][nt][i] = 0.f;

    LOAD_CHUNK(0, 0);

    int qd = lane & 3, r8 = lane >> 2;
    const int NCH = DD / 64;
    for (int kt = 0; kt < NCH; ++kt) {
        int buf = kt & 1;
        if (kt + 1 < NCH) {
            LOAD_CHUNK(kt + 1, buf ^ 1);
            cp_wait<1>();
        } else {
            cp_wait<0>();
        }
        __syncthreads();

#pragma unroll
        for (int ks = 0; ks < 4; ++ks) {
            uint32_t a[4][4], b[4][2];
#pragma unroll
            for (int mt = 0; mt < 4; ++mt)
                ldsm_x4(a[mt], aBase[buf] + 2 * (mt * 16 * SHH + ks * 16));
#pragma unroll
            for (int nt = 0; nt < 4; ++nt)
                ldsm_x2(b[nt], bBase[buf] + 2 * (nt * 8 * SHH + ks * 16));
#pragma unroll
            for (int mt = 0; mt < 4; ++mt)
#pragma unroll
                for (int nt = 0; nt < 4; ++nt)
                    mma_f16(acc[mt][nt], a[mt], b[nt]);
        }
        __syncthreads();
    }

#pragma unroll
    for (int mt = 0; mt < 4; ++mt) {
        int r0 = rowBase + wm * 64 + mt * 16 + r8;
#pragma unroll
        for (int nt = 0; nt < 4; ++nt) {
            int c = colBase + wn * 32 + nt * 8 + 2 * qd;
            float2 bv = *(const float2*)&bias[c];
            float2 o0, o1;
            o0.x = alpha * (acc[mt][nt][0] + bv.x);
            o0.y = alpha * (acc[mt][nt][1] + bv.y);
            o1.x = alpha * (acc[mt][nt][2] + bv.x);
            o1.y = alpha * (acc[mt][nt][3] + bv.y);
            if (out_mode == 2) {
                __half* Yh = (__half*)Yv;
                *(__half2*)&Yh[(size_t)r0 * DD + c]       = __floats2half2_rn(o0.x, o0.y);
                *(__half2*)&Yh[(size_t)(r0 + 8) * DD + c] = __floats2half2_rn(o1.x, o1.y);
            } else {
                float* Yf = (float*)Yv;
                *(float2*)&Yf[(size_t)r0 * DD + c] = o0;
                *(float2*)&Yf[(size_t)(r0 + 8) * DD + c] = o1;
            }
        }
    }
#undef LOAD_CHUNK
}

// ---------------- phi as FP16 MMA GEMM + fused max/exp -> fp16 out -------------
__global__ __launch_bounds__(256) void phi_gemm_kernel(
    const __half* __restrict__ proj, const float* __restrict__ rf,
    __half* __restrict__ out)
{
    extern __shared__ __half rfs[];   // [272][72]

    int tid = threadIdx.x;
    int lane = tid & 31, w = tid >> 5;
    int g0 = blockIdx.x * 128;

    for (int idx = tid; idx < 266 * 16; idx += 256) {
        int m = idx >> 4, q = (idx & 15) * 4;
        float4 v = *(const float4*)&rf[m * 64 + q];
        *(__half2*)&rfs[m * 72 + q]     = __floats2half2_rn(v.x, v.y);
        *(__half2*)&rfs[m * 72 + q + 2] = __floats2half2_rn(v.z, v.w);
    }
    for (int idx = tid; idx < 6 * 64; idx += 256) {
        int m = 266 + idx / 64, d = idx % 64;
        rfs[m * 72 + d] = __ushort_as_half((unsigned short)0);
    }

    int c = lane & 3, r = lane >> 2;
    int arow = w * 16 + r;
    int row0 = g0 + arow, row1 = row0 + 8;

    uint32_t x0h[8], x1h[8];
    const __half* p0 = proj + (size_t)row0 * 64;
    const __half* p1 = proj + (size_t)row1 * 64;
#pragma unroll
    for (int ks = 0; ks < 4; ++ks) {
        x0h[2 * ks]     = *(const uint32_t*)(p0 + ks * 16 + 2 * c);
        x0h[2 * ks + 1] = *(const uint32_t*)(p0 + ks * 16 + 8 + 2 * c);
        x1h[2 * ks]     = *(const uint32_t*)(p1 + ks * 16 + 2 * c);
        x1h[2 * ks + 1] = *(const uint32_t*)(p1 + ks * 16 + 8 + 2 * c);
    }

    float s0 = 0.f, s1 = 0.f;
#pragma unroll
    for (int j = 0; j < 8; ++j) {
        float2 f0 = __half22float2(*(const __half2*)&x0h[j]);
        float2 f1 = __half22float2(*(const __half2*)&x1h[j]);
        s0 += f0.x * f0.x + f0.y * f0.y;
        s1 += f1.x * f1.x + f1.y * f1.y;
    }
    s0 += __shfl_xor_sync(0xffffffffu, s0, 1);
    s0 += __shfl_xor_sync(0xffffffffu, s0, 2);
    s1 += __shfl_xor_sync(0xffffffffu, s1, 1);
    s1 += __shfl_xor_sync(0xffffffffu, s1, 2);
    float h0 = -0.5f * s0, h1 = -0.5f * s1;

    __syncthreads();

    float acc[34][4];
#pragma unroll
    for (int t = 0; t < 34; ++t)
#pragma unroll
        for (int i = 0; i < 4; ++i) acc[t][i] = 0.f;

#pragma unroll
    for (int ks = 0; ks < 4; ++ks) {
        uint32_t a[4];
        a[0] = x0h[2 * ks];
        a[1] = x1h[2 * ks];
        a[2] = x0h[2 * ks + 1];
        a[3] = x1h[2 * ks + 1];
#pragma unroll
        for (int t = 0; t < 34; ++t) {
            int br = t * 8 + r;
            uint32_t b[2];
            b[0] = *(const uint32_t*)(rfs + br * 72 + ks * 16 + 2 * c);
            b[1] = *(const uint32_t*)(rfs + br * 72 + ks * 16 + 8 + 2 * c);
            mma_f16(acc[t], a, b);
        }
    }

    float mx0 = -3.0e38f, mx1 = -3.0e38f;
#pragma unroll
    for (int t = 0; t < 34; ++t) {
        int c0 = t * 8 + 2 * c;
        if (c0 < 266)     { mx0 = fmaxf(mx0, acc[t][0]); mx1 = fmaxf(mx1, acc[t][2]); }
        if (c0 + 1 < 266) { mx0 = fmaxf(mx0, acc[t][1]); mx1 = fmaxf(mx1, acc[t][3]); }
    }
    mx0 = fmaxf(mx0, __shfl_xor_sync(0xffffffffu, mx0, 1));
    mx0 = fmaxf(mx0, __shfl_xor_sync(0xffffffffu, mx0, 2));
    mx1 = fmaxf(mx1, __shfl_xor_sync(0xffffffffu, mx1, 1));
    mx1 = fmaxf(mx1, __shfl_xor_sync(0xffffffffu, mx1, 2));

    int b0i = row0 >> 16, rem0 = row0 & 65535, l0 = rem0 >> 4, hh0 = rem0 & 15;
    int b1i = row1 >> 16, rem1 = row1 & 65535, l1 = rem1 >> 4, hh1 = rem1 & 15;
    __half* d0p = out + ((size_t)(b0i * 16 + hh0) * LL + l0) * MP;
    __half* d1p = out + ((size_t)(b1i * 16 + hh1) * LL + l1) * MP;

#pragma unroll
    for (int t = 0; t < 34; ++t) {
        int c0 = t * 8 + 2 * c;
        float v0x = (c0     < 266) ? __expf(h0 + acc[t][0] - mx0) * PHI_SCALE : 0.f;
        float v0y = (c0 + 1 < 266) ? __expf(h0 + acc[t][1] - mx0) * PHI_SCALE : 0.f;
        float v1x = (c0     < 266) ? __expf(h1 + acc[t][2] - mx1) * PHI_SCALE : 0.f;
        float v1y = (c0 + 1 < 266) ? __expf(h1 + acc[t][3] - mx1) * PHI_SCALE : 0.f;
        *(__half2*)&d0p[c0] = __floats2half2_rn(v0x, v0y);
        *(__half2*)&d1p[c0] = __floats2half2_rn(v1x, v1y);
    }
}

// ---------------- kv as FP16 MMA: kvT[d][m] = sum_l vT[d][l]*kp[l][m] ----------
// A = vT fp16 smem [80][40] (row64=ones), B = kp via ldmatrix.x2.trans.
__global__ __launch_bounds__(256) void kv_gemm_kernel(
    const __half* __restrict__ kp, const __half* __restrict__ vprojh,
    float* __restrict__ kvpart)
{
    __shared__ __align__(16) __half kps[32 * 280];   // [l][m] 17,920 B
    __shared__ __align__(16) __half vsT[80 * 40];    // [d][l]  6,400 B

    int tid = threadIdx.x;
    int lane = tid & 31, w = tid >> 5;
    int split = blockIdx.x, bh = blockIdx.y;
    int b = bh >> 4, h = bh & 15;
    int c = lane & 3, r = lane >> 2;

    // static rows: 64 = ones, 65..79 = 0
    for (int idx = tid; idx < 16 * 40; idx += 256) {
        int rr = idx / 40, l = idx % 40;
        vsT[(64 + rr) * 40 + l] = (rr == 0) ? __float2half(1.0f)
                                            : __ushort_as_half((unsigned short)0);
    }

    // ldmatrix.trans base: lanes 0-7 -> rows lane, 8-15 -> rows 8+(lane&7)
    int lrow_ldsm = (lane & 7) + ((lane & 8) ? 8 : 0);
    uint32_t kpsBase = (uint32_t)__cvta_generic_to_shared(kps) + 2 * (lrow_ldsm * 280);

    int ntiles = (w < 2) ? 5 : 4;
    float acc[5][5][4];
#pragma unroll
    for (int mt = 0; mt < 5; ++mt)
#pragma unroll
        for (int j = 0; j < 5; ++j)
#pragma unroll
            for (int i = 0; i < 4; ++i) acc[mt][j][i] = 0.f;

    int lbase = split * 1024;
    for (int ch = 0; ch < 32; ++ch) {
        int l0 = lbase + ch * 32;
        __syncthreads();
        // kp chunk [32][272] -> kps [32][280]
        for (int idx = tid; idx < 32 * 34; idx += 256) {
            int l = idx / 34, m8 = idx % 34;
            *(float4*)&kps[l * 280 + m8 * 8] =
                *(const float4*)&kp[((size_t)bh * LL + l0 + l) * MP + m8 * 8];
        }
        // v transpose: read half2 along d, write halves to vsT[d][l]
        for (int idx = tid; idx < 32 * 32; idx += 256) {
            int l = idx >> 5, d2 = idx & 31;
            __half2 v = *(const __half2*)&vprojh[((size_t)(b * LL + l0 + l)) * DD + h * DH + 2 * d2];
            vsT[(2 * d2 + 0) * 40 + l] = __low2half(v);
            vsT[(2 * d2 + 1) * 40 + l] = __high2half(v);
        }
        __syncthreads();

#pragma unroll
        for (int ks = 0; ks < 2; ++ks) {
            uint32_t a[5][4];
#pragma unroll
            for (int mt = 0; mt < 5; ++mt) {
                int ar = mt * 16 + r;
                a[mt][0] = *(const uint32_t*)(vsT + ar * 40 + ks * 16 + 2 * c);
                a[mt][1] = *(const uint32_t*)(vsT + (ar + 8) * 40 + ks * 16 + 2 * c);
                a[mt][2] = *(const uint32_t*)(vsT + ar * 40 + ks * 16 + 8 + 2 * c);
                a[mt][3] = *(const uint32_t*)(vsT + (ar + 8) * 40 + ks * 16 + 8 + 2 * c);
            }
#pragma unroll
            for (int j = 0; j < 5; ++j) {
                if (j >= ntiles) break;
                int t = (j < 4) ? (w + 8 * j) : (32 + w);
                uint32_t bfr[2];
                ldsm_x2_t(bfr, kpsBase + 2 * (ks * 16 * 280 + t * 8));
#pragma unroll
                for (int mt = 0; mt < 5; ++mt)
                    mma_f16(acc[mt][j], a[mt], bfr);
            }
        }
    }

    float* dst = kvpart + (size_t)(split * 64 + bh) * 80 * 272;
#pragma unroll
    for (int mt = 0; mt < 5; ++mt) {
        int d0 = mt * 16 + r;
#pragma unroll
        for (int j = 0; j < 5; ++j) {
            if (j >= ntiles) break;
            int t = (j < 4) ? (w + 8 * j) : (32 + w);
            int cc = t * 8 + 2 * c;
            *(float2*)&dst[d0 * 272 + cc]       = make_float2(acc[mt][j][0], acc[mt][j][1]);
            *(float2*)&dst[(d0 + 8) * 272 + cc] = make_float2(acc[mt][j][2], acc[mt][j][3]);
        }
    }
}

__global__ __launch_bounds__(256) void kv_reduce_kernel(
    const float* __restrict__ kvpart, __half* __restrict__ kvTh)
{
    int idx = blockIdx.x * 256 + threadIdx.x;
    const int total = 64 * 80 * 272;
    if (idx < total) {
        float s = kvpart[idx] + kvpart[total + idx]
                + kvpart[2 * total + idx] + kvpart[3 * total + idx];
        kvTh[idx] = __float2half_rn(s);
    }
}

// ---------------- ctx as FP16 MMA with fused denom -> fp16 out ------------------
// A = qp fp16 [l][m], B = kvT fp16 [d][m] (m contiguous -> direct frags).
__global__ __launch_bounds__(256) void ctx_gemm_kernel(
    const __half* __restrict__ qp, const __half* __restrict__ kvTh,
    __half* __restrict__ ctxh)
{
    extern __shared__ __align__(16) __half csm[];
    __half* kvs = csm;               // [80][280] 44,800 B
    __half* As  = csm + 80 * 280;    // [128][24]  6,144 B

    int tid = threadIdx.x;
    int lane = tid & 31, w = tid >> 5;
    int bh = blockIdx.y;
    int b = bh >> 4, h = bh & 15;
    int lblk = blockIdx.x * 128;
    int c = lane & 3, r = lane >> 2;

    for (int idx = tid; idx < 80 * 34; idx += 256) {
        int d = idx / 34, q = idx % 34;
        *(float4*)&kvs[d * 280 + q * 8] =
            *(const float4*)&kvTh[(size_t)bh * 80 * 272 + d * 272 + q * 8];
    }

    float acc[9][4];
#pragma unroll
    for (int t = 0; t < 9; ++t)
#pragma unroll
        for (int i = 0; i < 4; ++i) acc[t][i] = 0.f;

    int arow = w * 16 + r;

    for (int ch = 0; ch < 17; ++ch) {
        __syncthreads();
        {   // load qp chunk [128][16]
            int rr = tid >> 1, part = tid & 1;
            *(float4*)&As[rr * 24 + part * 8] =
                *(const float4*)&qp[((size_t)bh * LL + lblk + rr) * MP + ch * 16 + part * 8];
        }
        __syncthreads();

        uint32_t a[4];
        a[0] = *(const uint32_t*)(As + arow * 24 + 2 * c);
        a[1] = *(const uint32_t*)(As + (arow + 8) * 24 + 2 * c);
        a[2] = *(const uint32_t*)(As + arow * 24 + 8 + 2 * c);
        a[3] = *(const uint32_t*)(As + (arow + 8) * 24 + 8 + 2 * c);
#pragma unroll
        for (int t = 0; t < 9; ++t) {
            int br = t * 8 + r;
            uint32_t bfr[2];
            bfr[0] = *(const uint32_t*)(kvs + br * 280 + ch * 16 + 2 * c);
            bfr[1] = *(const uint32_t*)(kvs + br * 280 + ch * 16 + 8 + 2 * c);
            mma_f16(acc[t], a, bfr);
        }
    }

    // denom: n-tile 8, col 64 -> lanes with c==0 hold it
    float den0 = __shfl_sync(0xffffffffu, acc[8][0], lane & ~3);
    float den1 = __shfl_sync(0xffffffffu, acc[8][2], lane & ~3);
    float inv0 = 1.0f / (den0 + 1e-6f);
    float inv1 = 1.0f / (den1 + 1e-6f);

    int lrow0 = lblk + arow, lrow1 = lblk + arow + 8;
    __half* o0 = ctxh + ((size_t)(b * LL + lrow0)) * DD + h * DH;
    __half* o1 = ctxh + ((size_t)(b * LL + lrow1)) * DD + h * DH;
#pragma unroll
    for (int t = 0; t < 8; ++t) {
        int cc = t * 8 + 2 * c;
        *(__half2*)&o0[cc] = __floats2half2_rn(acc[t][0] * inv0, acc[t][1] * inv0);
        *(__half2*)&o1[cc] = __floats2half2_rn(acc[t][2] * inv1, acc[t][3] * inv1);
    }
}

// ---------------- host launcher ------------------------------------------------
extern "C" void kernel_launch(void* const* d_in, const int* in_sizes, int n_in,
                              void* d_out, int out_size)
{
    const float* query = (const float*)d_in[0];
    const float* key   = (const float*)d_in[1];
    const float* value = (const float*)d_in[2];
    const float* q_w   = (const float*)d_in[3];
    const float* q_b   = (const float*)d_in[4];
    const float* k_w   = (const float*)d_in[5];
    const float* k_b   = (const float*)d_in[6];
    const float* v_w   = (const float*)d_in[7];
    const float* v_b   = (const float*)d_in[8];
    const float* out_w = (const float*)d_in[9];
    const float* out_b = (const float*)d_in[10];
    const float* rf    = (const float*)d_in[11];
    float* out = (float*)d_out;

    __half *p_qh, *p_kh, *p_vh, *p_wqh, *p_wkh, *p_wvh, *p_woh, *p_ctxh;
    __half *p_qprojh, *p_kprojh, *p_vprojh, *p_qp, *p_kp, *p_kvT;
    float *p_kvpart;
    cudaGetSymbolAddress((void**)&p_qh, g_qh);
    cudaGetSymbolAddress((void**)&p_kh, g_kh);
    cudaGetSymbolAddress((void**)&p_vh, g_vh);
    cudaGetSymbolAddress((void**)&p_wqh, g_wqh);
    cudaGetSymbolAddress((void**)&p_wkh, g_wkh);
    cudaGetSymbolAddress((void**)&p_wvh, g_wvh);
    cudaGetSymbolAddress((void**)&p_woh, g_woh);
    cudaGetSymbolAddress((void**)&p_ctxh, g_ctxh);
    cudaGetSymbolAddress((void**)&p_qprojh, g_qprojh);
    cudaGetSymbolAddress((void**)&p_kprojh, g_kprojh);
    cudaGetSymbolAddress((void**)&p_vprojh, g_vprojh);
    cudaGetSymbolAddress((void**)&p_qp, g_qp);
    cudaGetSymbolAddress((void**)&p_kp, g_kp);
    cudaGetSymbolAddress((void**)&p_kvpart, g_kvpart);
    cudaGetSymbolAddress((void**)&p_kvT, g_kvT);

    int gemm_smem = 4 * 128 * SHH * sizeof(__half);            // 73,728 B
    int phi_smem  = 272 * 72 * sizeof(__half);                 // 39,168 B
    int ctx_smem  = (80 * 280 + 128 * 24) * sizeof(__half);    // 50,944 B
    cudaFuncSetAttribute(gemm_fp16_kernel, cudaFuncAttributeMaxDynamicSharedMemorySize, gemm_smem);
    cudaFuncSetAttribute(phi_gemm_kernel,  cudaFuncAttributeMaxDynamicSharedMemorySize, phi_smem);
    cudaFuncSetAttribute(ctx_gemm_kernel,  cudaFuncAttributeMaxDynamicSharedMemorySize, ctx_smem);

    const int NB = NROWS * DD / 4;
    const int WB = DD * DD / 4;
    dim3 gemmGrid(DD / 128, NROWS / 128);

    f2h_kernel<<<(NB + 255) / 256, 256>>>((const float4*)query, (__half2*)p_qh, NB);   // 0
    f2h_kernel<<<(WB + 255) / 256, 256>>>((const float4*)q_w,   (__half2*)p_wqh, WB);  // 1
    f2h_kernel<<<(NB + 255) / 256, 256>>>((const float4*)key,   (__half2*)p_kh, NB);   // 2
    f2h_kernel<<<(WB + 255) / 256, 256>>>((const float4*)k_w,   (__half2*)p_wkh, WB);  // 3
    f2h_kernel<<<(NB + 255) / 256, 256>>>((const float4*)value, (__half2*)p_vh, NB);   // 4
    gemm_fp16_kernel<<<gemmGrid, 256, gemm_smem>>>(p_qh, p_wqh, q_b, p_qprojh, QK_SCALE, 2);  // 5
    f2h_kernel<<<(WB + 255) / 256, 256>>>((const float4*)v_w,   (__half2*)p_wvh, WB);  // 6
    f2h_kernel<<<(WB + 255) / 256, 256>>>((const float4*)out_w, (__half2*)p_woh, WB);  // 7
    gemm_fp16_kernel<<<gemmGrid, 256, gemm_smem>>>(p_kh, p_wkh, k_b, p_kprojh, QK_SCALE, 2);
    gemm_fp16_kernel<<<gemmGrid, 256, gemm_smem>>>(p_vh, p_wvh, v_b, p_vprojh, 1.0f, 2);

    phi_gemm_kernel<<<GROWS / 128, 256, phi_smem>>>(p_qprojh, rf, p_qp);
    phi_gemm_kernel<<<GROWS / 128, 256, phi_smem>>>(p_kprojh, rf, p_kp);

    dim3 kvGrid(4, BB * HH);
    kv_gemm_kernel<<<kvGrid, 256>>>(p_kp, p_vprojh, p_kvpart);
    kv_reduce_kernel<<<(64 * 80 * 272 + 255) / 256, 256>>>(p_kvpart, p_kvT);

    dim3 ctxGrid(LL / 128, BB * HH);
    ctx_gemm_kernel<<<ctxGrid, 256, ctx_smem>>>(p_qp, p_kvT, p_ctxh);

    gemm_fp16_kernel<<<gemmGrid, 256, gemm_smem>>>(p_ctxh, p_woh, out_b, out, 1.0f, 0);
}